// round 11
// baseline (speedup 1.0000x reference)
#include <cuda_runtime.h>
#include <cuda_bf16.h>
#include <cstdint>
#include <math.h>

#define NB 4
#define NT 24
#define NP 4096
#define MM 128
#define TO 12
#define LTOK 1536
#define NTOK 6144
#define EDIM 512
#define NHEAD 8
#define DHEAD 64
#define MLPD 1024
#define NCLS 30
#define KSAMP 32
#define RAD2 0.09f

#define CONTR_OFF 120
#define FEAT_OFF (120 + NTOK*EDIM)

// weight-split buffer offsets (elements)
#define WQKV_OFF 0
#define WOUT_OFF 3145728
#define WFF1_OFF 4194304
#define WFF2_OFF 6291456
#define WTOT     8388608

// ---------------- scratch (device globals; no cudaMalloc allowed) ----------
__device__ __align__(256) float g_anchor[NTOK*3];
__device__ __align__(256) int   g_ball[3*NTOK*KSAMP];
__device__ __align__(256) float g_x[NTOK*EDIM];
__device__ __align__(256) float g_featp[3*NTOK*EDIM];
__device__ __align__(256) float g_pool[NB*EDIM];
__device__ __align__(256) float g_poolp[NB*12*EDIM];
__device__ __align__(256) float g_hln[NB*EDIM];
__device__ __align__(256) float g_h1[NB*MLPD];

__device__ __align__(256) __nv_bfloat16 g_wh[WTOT];
__device__ __align__(256) __nv_bfloat16 g_wl[WTOT];
__device__ __align__(256) __nv_bfloat16 g_hh[NTOK*EDIM];
__device__ __align__(256) __nv_bfloat16 g_hl[NTOK*EDIM];
__device__ __align__(256) __nv_bfloat16 g_qh[NTOK*1536];
__device__ __align__(256) __nv_bfloat16 g_ql[NTOK*1536];
__device__ __align__(256) __nv_bfloat16 g_oh[NTOK*EDIM];
__device__ __align__(256) __nv_bfloat16 g_ol[NTOK*EDIM];
__device__ __align__(256) __nv_bfloat16 g_f1h[NTOK*MLPD];
__device__ __align__(256) __nv_bfloat16 g_f1l[NTOK*MLPD];

__device__ __forceinline__ float gelu_exact(float x){
    return 0.5f*x*(1.0f+erff(x*0.70710678118654752440f));
}

// ==================== PTX helpers ==========================================
__device__ __forceinline__ void mma16816(float* c, const unsigned* a, const unsigned* b){
    asm volatile("mma.sync.aligned.m16n8k16.row.col.f32.bf16.bf16.f32 "
        "{%0,%1,%2,%3}, {%4,%5,%6,%7}, {%8,%9}, {%0,%1,%2,%3};"
        : "+f"(c[0]),"+f"(c[1]),"+f"(c[2]),"+f"(c[3])
        : "r"(a[0]),"r"(a[1]),"r"(a[2]),"r"(a[3]), "r"(b[0]),"r"(b[1]));
}
__device__ __forceinline__ void split2(float x, float y, unsigned& hi, unsigned& lo){
    __nv_bfloat16 hx = __float2bfloat16(x), hy = __float2bfloat16(y);
    float rx = x - __bfloat162float(hx), ry = y - __bfloat162float(hy);
    __nv_bfloat16 lx = __float2bfloat16(rx), ly = __float2bfloat16(ry);
    hi = (unsigned)__bfloat16_as_ushort(hx) | ((unsigned)__bfloat16_as_ushort(hy) << 16);
    lo = (unsigned)__bfloat16_as_ushort(lx) | ((unsigned)__bfloat16_as_ushort(ly) << 16);
}
__device__ __forceinline__ unsigned smem_u32(const void* p){
    unsigned a;
    asm("{ .reg .u64 t; cvta.to.shared.u64 t, %1; cvt.u32.u64 %0, t; }" : "=r"(a) : "l"(p));
    return a;
}
__device__ __forceinline__ void ldmx4(unsigned* r, unsigned addr){
    asm volatile("ldmatrix.sync.aligned.m8n8.x4.shared.b16 {%0,%1,%2,%3}, [%4];"
        : "=r"(r[0]),"=r"(r[1]),"=r"(r[2]),"=r"(r[3]) : "r"(addr));
}
__device__ __forceinline__ void ldmx4t(unsigned* r, unsigned addr){
    asm volatile("ldmatrix.sync.aligned.m8n8.x4.trans.shared.b16 {%0,%1,%2,%3}, [%4];"
        : "=r"(r[0]),"=r"(r[1]),"=r"(r[2]),"=r"(r[3]) : "r"(addr));
}
#define CP16(d, s) asm volatile("cp.async.cg.shared.global [%0], [%1], 16;" :: "r"(d), "l"(s) : "memory")
#define CPC() asm volatile("cp.async.commit_group;" ::: "memory")
#define CPW0() asm volatile("cp.async.wait_group 0;" ::: "memory")

// ---------------- fused weight split prep (single launch) -------------------
__global__ __launch_bounds__(256) void wsplit_all_kernel(
    const float* __restrict__ qkv_w, const float* __restrict__ out_w,
    const float* __restrict__ ff1_w, const float* __restrict__ ff2_w,
    __nv_bfloat16* __restrict__ hi, __nv_bfloat16* __restrict__ lo)
{
    int i = (blockIdx.x*256 + threadIdx.x)*4;
    if (i >= WTOT) return;
    const float* src;
    int off;
    if (i < WOUT_OFF)       { src = qkv_w; off = i - WQKV_OFF; }
    else if (i < WFF1_OFF)  { src = out_w; off = i - WOUT_OFF; }
    else if (i < WFF2_OFF)  { src = ff1_w; off = i - WFF1_OFF; }
    else                    { src = ff2_w; off = i - WFF2_OFF; }
    float4 v = *(const float4*)(src + off);
    unsigned h0, l0, h1, l1;
    split2(v.x, v.y, h0, l0); split2(v.z, v.w, h1, l1);
    *(unsigned*)(hi+i) = h0; *(unsigned*)(hi+i+2) = h1;
    *(unsigned*)(lo+i) = l0; *(unsigned*)(lo+i+2) = l1;
}

#define LDT 40                       // smem row stride in bf16 (32 + 8 pad)
#define GARR (128*LDT*2)             // 10240 B per 128-row array
#define GSTAGE (4*GARR)              // 40960 B per stage
#define G_SMEM (2*GSTAGE)            // 81920 B

// ============ GEMM BN=128, pre-split bf16, cp.async, ldmatrix ==============
__global__ __launch_bounds__(256) void tgemm_b(
    const __nv_bfloat16* __restrict__ AH_, const __nv_bfloat16* __restrict__ AL_,
    const __nv_bfloat16* __restrict__ WH_, const __nv_bfloat16* __restrict__ WL_,
    const float* __restrict__ bias, float* __restrict__ Cf,
    __nv_bfloat16* __restrict__ CH_, __nv_bfloat16* __restrict__ CL_,
    int K, int lda, int ldw, int ldc,
    int act, int resid, int hasb, int split, int qscale)
{
    extern __shared__ char smem[];
    unsigned sb = smem_u32(smem);

    int tid = threadIdx.x, wid = tid >> 5, lane = tid & 31;
    int g = lane >> 2, tg = lane & 3;
    int q8 = lane >> 3, lr8 = lane & 7;
    int rw = (wid >> 2) * 64, cw = (wid & 3) * 32;
    int bm = blockIdx.y * 128, bn = blockIdx.x * 128;

    float acc[4][4][4];
    #pragma unroll
    for (int i = 0; i < 4; i++)
        #pragma unroll
        for (int j = 0; j < 4; j++)
            #pragma unroll
            for (int p = 0; p < 4; p++) acc[i][j][p] = 0.f;

    int row = tid >> 1, half = tid & 1;
    int nch = K >> 5;

    {
        unsigned dst = sb + (row*LDT + half*16)*2;
        const __nv_bfloat16* a = AH_ + (size_t)(bm+row)*lda + half*16;
        const __nv_bfloat16* a2 = AL_ + (size_t)(bm+row)*lda + half*16;
        const __nv_bfloat16* w = WH_ + (size_t)(bn+row)*ldw + half*16;
        const __nv_bfloat16* w2 = WL_ + (size_t)(bn+row)*ldw + half*16;
        CP16(dst, a); CP16(dst+16, a+8);
        CP16(dst+GARR, a2); CP16(dst+GARR+16, a2+8);
        CP16(dst+2*GARR, w); CP16(dst+2*GARR+16, w+8);
        CP16(dst+3*GARR, w2); CP16(dst+3*GARR+16, w2+8);
        CPC();
    }

    for (int c = 0; c < nch; c++) {
        CPW0();
        __syncthreads();
        if (c + 1 < nch) {
            unsigned dst = sb + ((c+1)&1)*GSTAGE + (row*LDT + half*16)*2;
            const __nv_bfloat16* a = AH_ + (size_t)(bm+row)*lda + (c+1)*32 + half*16;
            const __nv_bfloat16* a2 = AL_ + (size_t)(bm+row)*lda + (c+1)*32 + half*16;
            const __nv_bfloat16* w = WH_ + (size_t)(bn+row)*ldw + (c+1)*32 + half*16;
            const __nv_bfloat16* w2 = WL_ + (size_t)(bn+row)*ldw + (c+1)*32 + half*16;
            CP16(dst, a); CP16(dst+16, a+8);
            CP16(dst+GARR, a2); CP16(dst+GARR+16, a2+8);
            CP16(dst+2*GARR, w); CP16(dst+2*GARR+16, w+8);
            CP16(dst+3*GARR, w2); CP16(dst+3*GARR+16, w2+8);
            CPC();
        }
        unsigned sAH = sb + (c&1)*GSTAGE;
        unsigned sAL = sAH + GARR;
        unsigned sWH = sAH + 2*GARR;
        unsigned sWL = sAH + 3*GARR;
        #pragma unroll
        for (int ks = 0; ks < 2; ks++) {
            int k0 = ks * 16;
            unsigned ah[4][4], al[4][4], bh[2][4], bl[2][4];
            #pragma unroll
            for (int mt = 0; mt < 4; mt++) {
                unsigned off = (unsigned)((rw + mt*16 + (q8&1)*8 + lr8)*LDT + k0 + (q8>>1)*8)*2;
                ldmx4(ah[mt], sAH + off);
                ldmx4(al[mt], sAL + off);
            }
            #pragma unroll
            for (int ntp = 0; ntp < 2; ntp++) {
                unsigned off = (unsigned)((cw + ntp*16 + (q8>>1)*8 + lr8)*LDT + k0 + (q8&1)*8)*2;
                ldmx4(bh[ntp], sWH + off);
                ldmx4(bl[ntp], sWL + off);
            }
            #pragma unroll
            for (int mt = 0; mt < 4; mt++)
                #pragma unroll
                for (int nt = 0; nt < 4; nt++) {
                    const unsigned* ph = &bh[nt>>1][(nt&1)*2];
                    const unsigned* pl = &bl[nt>>1][(nt&1)*2];
                    mma16816(acc[mt][nt], ah[mt], ph);
                    mma16816(acc[mt][nt], ah[mt], pl);
                    mma16816(acc[mt][nt], al[mt], ph);
                }
        }
    }
    #pragma unroll
    for (int mt = 0; mt < 4; mt++) {
        #pragma unroll
        for (int nt = 0; nt < 4; nt++) {
            int r0 = bm + rw + mt*16 + g;
            int col = bn + cw + nt*8 + tg*2;
            #pragma unroll
            for (int half2 = 0; half2 < 2; half2++) {
                int r = r0 + half2*8;
                float v0 = acc[mt][nt][half2*2+0];
                float v1 = acc[mt][nt][half2*2+1];
                if (hasb) { v0 += bias[col]; v1 += bias[col+1]; }
                if (act)  { v0 = gelu_exact(v0); v1 = gelu_exact(v1); }
                if (split) {
                    if (qscale && col < 512) { v0 *= 0.125f; v1 *= 0.125f; }
                    unsigned hh, ll;
                    split2(v0, v1, hh, ll);
                    *(unsigned*)(CH_ + (size_t)r*ldc + col) = hh;
                    *(unsigned*)(CL_ + (size_t)r*ldc + col) = ll;
                } else {
                    float* cp = Cf + (size_t)r * ldc + col;
                    if (resid) {
                        float2 old = *(float2*)cp;
                        v0 += old.x; v1 += old.y;
                    }
                    float2 ov = {v0, v1};
                    *(float2*)cp = ov;
                }
            }
        }
    }
}

// ============ GEMM BN=64 (wave fill for narrow N) ==========================
#define G64_WARR (64*LDT*2)              // 5120 B
#define G64_STAGE (2*GARR + 2*G64_WARR)  // 30720 B
#define G64_SMEM (2*G64_STAGE)           // 61440 B

__global__ __launch_bounds__(256) void tgemm_b64(
    const __nv_bfloat16* __restrict__ AH_, const __nv_bfloat16* __restrict__ AL_,
    const __nv_bfloat16* __restrict__ WH_, const __nv_bfloat16* __restrict__ WL_,
    const float* __restrict__ bias, float* __restrict__ Cf,
    __nv_bfloat16* __restrict__ CH_, __nv_bfloat16* __restrict__ CL_,
    int K, int lda, int ldw, int ldc,
    int act, int resid, int hasb, int split)
{
    extern __shared__ char smem[];
    unsigned sb = smem_u32(smem);

    int tid = threadIdx.x, wid = tid >> 5, lane = tid & 31;
    int g = lane >> 2, tg = lane & 3;
    int q8 = lane >> 3, lr8 = lane & 7;
    int rw = (wid >> 2) * 64, cw = (wid & 3) * 16;
    int bm = blockIdx.y * 128, bn = blockIdx.x * 64;

    float acc[4][2][4];
    #pragma unroll
    for (int i = 0; i < 4; i++)
        #pragma unroll
        for (int j = 0; j < 2; j++)
            #pragma unroll
            for (int p = 0; p < 4; p++) acc[i][j][p] = 0.f;

    int row = tid >> 1, half = tid & 1;
    int roww = tid >> 2, colq = (tid & 3) * 8;
    int nch = K >> 5;

    {
        unsigned dstA = sb + (row*LDT + half*16)*2;
        const __nv_bfloat16* a = AH_ + (size_t)(bm+row)*lda + half*16;
        const __nv_bfloat16* a2 = AL_ + (size_t)(bm+row)*lda + half*16;
        CP16(dstA, a); CP16(dstA+16, a+8);
        CP16(dstA+GARR, a2); CP16(dstA+GARR+16, a2+8);
        unsigned dstW = sb + 2*GARR + (roww*LDT + colq)*2;
        const __nv_bfloat16* w = WH_ + (size_t)(bn+roww)*ldw + colq;
        const __nv_bfloat16* w2 = WL_ + (size_t)(bn+roww)*ldw + colq;
        CP16(dstW, w);
        CP16(dstW+G64_WARR, w2);
        CPC();
    }

    for (int c = 0; c < nch; c++) {
        CPW0();
        __syncthreads();
        if (c + 1 < nch) {
            unsigned st = ((c+1)&1)*G64_STAGE;
            unsigned dstA = sb + st + (row*LDT + half*16)*2;
            const __nv_bfloat16* a = AH_ + (size_t)(bm+row)*lda + (c+1)*32 + half*16;
            const __nv_bfloat16* a2 = AL_ + (size_t)(bm+row)*lda + (c+1)*32 + half*16;
            CP16(dstA, a); CP16(dstA+16, a+8);
            CP16(dstA+GARR, a2); CP16(dstA+GARR+16, a2+8);
            unsigned dstW = sb + st + 2*GARR + (roww*LDT + colq)*2;
            const __nv_bfloat16* w = WH_ + (size_t)(bn+roww)*ldw + (c+1)*32 + colq;
            const __nv_bfloat16* w2 = WL_ + (size_t)(bn+roww)*ldw + (c+1)*32 + colq;
            CP16(dstW, w);
            CP16(dstW+G64_WARR, w2);
            CPC();
        }
        unsigned sAH = sb + (c&1)*G64_STAGE;
        unsigned sAL = sAH + GARR;
        unsigned sWH = sAH + 2*GARR;
        unsigned sWL = sWH + G64_WARR;
        #pragma unroll
        for (int ks = 0; ks < 2; ks++) {
            int k0 = ks * 16;
            unsigned ah[4][4], al[4][4], bh4[4], bl4[4];
            #pragma unroll
            for (int mt = 0; mt < 4; mt++) {
                unsigned off = (unsigned)((rw + mt*16 + (q8&1)*8 + lr8)*LDT + k0 + (q8>>1)*8)*2;
                ldmx4(ah[mt], sAH + off);
                ldmx4(al[mt], sAL + off);
            }
            {
                unsigned off = (unsigned)((cw + (q8>>1)*8 + lr8)*LDT + k0 + (q8&1)*8)*2;
                ldmx4(bh4, sWH + off);
                ldmx4(bl4, sWL + off);
            }
            #pragma unroll
            for (int mt = 0; mt < 4; mt++)
                #pragma unroll
                for (int nt = 0; nt < 2; nt++) {
                    mma16816(acc[mt][nt], ah[mt], bh4 + nt*2);
                    mma16816(acc[mt][nt], ah[mt], bl4 + nt*2);
                    mma16816(acc[mt][nt], al[mt], bh4 + nt*2);
                }
        }
    }
    #pragma unroll
    for (int mt = 0; mt < 4; mt++) {
        #pragma unroll
        for (int nt = 0; nt < 2; nt++) {
            int r0 = bm + rw + mt*16 + g;
            int col = bn + cw + nt*8 + tg*2;
            #pragma unroll
            for (int half2 = 0; half2 < 2; half2++) {
                int r = r0 + half2*8;
                float v0 = acc[mt][nt][half2*2+0];
                float v1 = acc[mt][nt][half2*2+1];
                if (hasb) { v0 += bias[col]; v1 += bias[col+1]; }
                if (act)  { v0 = gelu_exact(v0); v1 = gelu_exact(v1); }
                if (split) {
                    unsigned hh, ll;
                    split2(v0, v1, hh, ll);
                    *(unsigned*)(CH_ + (size_t)r*ldc + col) = hh;
                    *(unsigned*)(CL_ + (size_t)r*ldc + col) = ll;
                } else {
                    float* cp = Cf + (size_t)r * ldc + col;
                    if (resid) {
                        float2 old = *(float2*)cp;
                        v0 += old.x; v1 += old.y;
                    }
                    float2 ov = {v0, v1};
                    *(float2*)cp = ov;
                }
            }
        }
    }
}

// ==================== flash attention ======================================
#define FQS 72
#define FARR (128*FQS*2)             // 18432 B
#define FQH 0
#define FQL FARR
#define FST(s) (2*FARR + (s)*4*FARR)
#define FA_SMEM (2*FARR + 2*4*FARR)  // 184320 B

__global__ __launch_bounds__(256) void flash_kernel(
    const __nv_bfloat16* __restrict__ qh, const __nv_bfloat16* __restrict__ ql,
    __nv_bfloat16* __restrict__ oh, __nv_bfloat16* __restrict__ ol)
{
    extern __shared__ char fsm[];
    unsigned sb = smem_u32(fsm);

    int tid = threadIdx.x, wid = tid >> 5, lane = tid & 31;
    int g = lane >> 2, tg = lane & 3;
    int q8 = lane >> 3, lr8 = lane & 7;
    int z = blockIdx.y;
    int b = z >> 3, h = z & 7;
    size_t base = (size_t)b * LTOK * 1536;
    int q0 = blockIdx.x * 128;

    int row = tid >> 1, half = tid & 1;

    {
        unsigned dq = sb + (row*FQS + half*32)*2;
        const __nv_bfloat16* sq = qh + base + (size_t)(q0+row)*1536 + h*64 + half*32;
        const __nv_bfloat16* sq2 = ql + base + (size_t)(q0+row)*1536 + h*64 + half*32;
        #pragma unroll
        for (int j = 0; j < 4; j++) {
            CP16(dq + j*16, sq + j*8);
            CP16(dq + FARR + j*16, sq2 + j*8);
        }
        unsigned dk = sb + FST(0) + (row*FQS + half*32)*2;
        const __nv_bfloat16* sk = qh + base + (size_t)row*1536 + 512 + h*64 + half*32;
        const __nv_bfloat16* sk2 = ql + base + (size_t)row*1536 + 512 + h*64 + half*32;
        const __nv_bfloat16* sv = qh + base + (size_t)row*1536 + 1024 + h*64 + half*32;
        const __nv_bfloat16* sv2 = ql + base + (size_t)row*1536 + 1024 + h*64 + half*32;
        #pragma unroll
        for (int j = 0; j < 4; j++) {
            CP16(dk + j*16, sk + j*8);
            CP16(dk + FARR + j*16, sk2 + j*8);
            CP16(dk + 2*FARR + j*16, sv + j*8);
            CP16(dk + 3*FARR + j*16, sv2 + j*8);
        }
        CPC();
    }

    float acco[8][4];
    #pragma unroll
    for (int i = 0; i < 8; i++)
        #pragma unroll
        for (int p = 0; p < 4; p++) acco[i][p] = 0.f;
    float m0 = -3.402823466e38f, m1 = -3.402823466e38f, l0s = 0.f, l1s = 0.f;

    for (int t = 0; t < LTOK/128; t++) {
        CPW0();
        __syncthreads();
        if (t + 1 < LTOK/128) {
            unsigned dk = sb + FST((t+1)&1) + (row*FQS + half*32)*2;
            size_t ro = base + (size_t)((t+1)*128+row)*1536 + h*64 + half*32;
            const __nv_bfloat16* sk = qh + ro + 512;
            const __nv_bfloat16* sk2 = ql + ro + 512;
            const __nv_bfloat16* sv = qh + ro + 1024;
            const __nv_bfloat16* sv2 = ql + ro + 1024;
            #pragma unroll
            for (int j = 0; j < 4; j++) {
                CP16(dk + j*16, sk + j*8);
                CP16(dk + FARR + j*16, sk2 + j*8);
                CP16(dk + 2*FARR + j*16, sv + j*8);
                CP16(dk + 3*FARR + j*16, sv2 + j*8);
            }
            CPC();
        }
        unsigned sKH = sb + FST(t&1);
        unsigned sKL = sKH + FARR;
        unsigned sVH = sKH + 2*FARR;
        unsigned sVL = sKH + 3*FARR;

        float accs[16][4];
        #pragma unroll
        for (int nt = 0; nt < 16; nt++)
            #pragma unroll
            for (int p = 0; p < 4; p++) accs[nt][p] = 0.f;
        #pragma unroll
        for (int ks = 0; ks < 4; ks++) {
            int k0 = ks*16;
            unsigned aqh[4], aql[4];
            unsigned aoff = (unsigned)((wid*16 + (q8&1)*8 + lr8)*FQS + k0 + (q8>>1)*8)*2;
            ldmx4(aqh, sb + FQH + aoff);
            ldmx4(aql, sb + FQL + aoff);
            #pragma unroll
            for (int ntp = 0; ntp < 8; ntp++) {
                unsigned boff = (unsigned)((ntp*16 + (q8>>1)*8 + lr8)*FQS + k0 + (q8&1)*8)*2;
                unsigned bh4[4], bl4[4];
                ldmx4(bh4, sKH + boff);
                ldmx4(bl4, sKL + boff);
                mma16816(accs[2*ntp],   aqh, bh4);
                mma16816(accs[2*ntp],   aqh, bl4);
                mma16816(accs[2*ntp],   aql, bh4);
                mma16816(accs[2*ntp+1], aqh, bh4+2);
                mma16816(accs[2*ntp+1], aqh, bl4+2);
                mma16816(accs[2*ntp+1], aql, bh4+2);
            }
        }

        float mx0 = -3.402823466e38f, mx1 = -3.402823466e38f;
        #pragma unroll
        for (int nt = 0; nt < 16; nt++) {
            mx0 = fmaxf(mx0, fmaxf(accs[nt][0], accs[nt][1]));
            mx1 = fmaxf(mx1, fmaxf(accs[nt][2], accs[nt][3]));
        }
        mx0 = fmaxf(mx0, __shfl_xor_sync(0xffffffffu, mx0, 1));
        mx0 = fmaxf(mx0, __shfl_xor_sync(0xffffffffu, mx0, 2));
        mx1 = fmaxf(mx1, __shfl_xor_sync(0xffffffffu, mx1, 1));
        mx1 = fmaxf(mx1, __shfl_xor_sync(0xffffffffu, mx1, 2));
        float mn0 = fmaxf(m0, mx0), mn1 = fmaxf(m1, mx1);
        float c0 = __expf(m0 - mn0), c1 = __expf(m1 - mn1);
        float s0 = 0.f, s1 = 0.f;
        #pragma unroll
        for (int nt = 0; nt < 16; nt++) {
            accs[nt][0] = __expf(accs[nt][0] - mn0);
            accs[nt][1] = __expf(accs[nt][1] - mn0);
            accs[nt][2] = __expf(accs[nt][2] - mn1);
            accs[nt][3] = __expf(accs[nt][3] - mn1);
            s0 += accs[nt][0] + accs[nt][1];
            s1 += accs[nt][2] + accs[nt][3];
        }
        s0 += __shfl_xor_sync(0xffffffffu, s0, 1);
        s0 += __shfl_xor_sync(0xffffffffu, s0, 2);
        s1 += __shfl_xor_sync(0xffffffffu, s1, 1);
        s1 += __shfl_xor_sync(0xffffffffu, s1, 2);
        l0s = l0s * c0 + s0;
        l1s = l1s * c1 + s1;
        m0 = mn0; m1 = mn1;
        #pragma unroll
        for (int i = 0; i < 8; i++) {
            acco[i][0] *= c0; acco[i][1] *= c0;
            acco[i][2] *= c1; acco[i][3] *= c1;
        }

        #pragma unroll
        for (int pks = 0; pks < 8; pks++) {
            unsigned aph[4], apl[4];
            split2(accs[2*pks][0],   accs[2*pks][1],   aph[0], apl[0]);
            split2(accs[2*pks][2],   accs[2*pks][3],   aph[1], apl[1]);
            split2(accs[2*pks+1][0], accs[2*pks+1][1], aph[2], apl[2]);
            split2(accs[2*pks+1][2], accs[2*pks+1][3], aph[3], apl[3]);
            #pragma unroll
            for (int ntp2 = 0; ntp2 < 4; ntp2++) {
                unsigned voff = (unsigned)((pks*16 + (q8&1)*8 + lr8)*FQS + ntp2*16 + (q8>>1)*8)*2;
                unsigned bvh[4], bvl[4];
                ldmx4t(bvh, sVH + voff);
                ldmx4t(bvl, sVL + voff);
                mma16816(acco[2*ntp2],   aph, bvh);
                mma16816(acco[2*ntp2],   aph, bvl);
                mma16816(acco[2*ntp2],   apl, bvh);
                mma16816(acco[2*ntp2+1], aph, bvh+2);
                mma16816(acco[2*ntp2+1], aph, bvl+2);
                mma16816(acco[2*ntp2+1], apl, bvh+2);
            }
        }
    }

    float inv0 = 1.0f / l0s, inv1 = 1.0f / l1s;
    int orow = q0 + wid*16 + g;
    #pragma unroll
    for (int nt2 = 0; nt2 < 8; nt2++) {
        int col = h*64 + nt2*8 + tg*2;
        unsigned hh, ll;
        split2(acco[nt2][0]*inv0, acco[nt2][1]*inv0, hh, ll);
        *(unsigned*)(oh + (size_t)(b*LTOK + orow) * EDIM + col) = hh;
        *(unsigned*)(ol + (size_t)(b*LTOK + orow) * EDIM + col) = ll;
        split2(acco[nt2][2]*inv1, acco[nt2][3]*inv1, hh, ll);
        *(unsigned*)(oh + (size_t)(b*LTOK + orow + 8) * EDIM + col) = hh;
        *(unsigned*)(ol + (size_t)(b*LTOK + orow + 8) * EDIM + col) = ll;
    }
}

// ---------------- FPS -------------------------------------------------------
__global__ __launch_bounds__(512) void fps_kernel(const float* __restrict__ xyzs) {
    int blk = blockIdx.x;
    int b = blk / TO, j = blk % TO;
    const float* P = xyzs + (size_t)(b*NT + 2*j)*NP*3;
    int tid = threadIdx.x;
    float px[8], py[8], pz[8], dist[8];
    #pragma unroll
    for (int i = 0; i < 8; i++) {
        int p = tid + i*512;
        px[i] = P[p*3+0]; py[i] = P[p*3+1]; pz[i] = P[p*3+2];
        dist[i] = 1e10f;
    }
    __shared__ float sbx, sby, sbz;
    __shared__ float swv[16];
    __shared__ int   swi[16];
    float* anch = g_anchor + (size_t)blk*MM*3;
    if (tid == 0) {
        sbx = P[0]; sby = P[1]; sbz = P[2];
        anch[0] = P[0]; anch[1] = P[1]; anch[2] = P[2];
    }
    __syncthreads();
    for (int s = 1; s < MM; s++) {
        float bx = sbx, by = sby, bz = sbz;
        float bestv = -1.0f; int besti = 0x7fffffff;
        #pragma unroll
        for (int i = 0; i < 8; i++) {
            float dx = __fsub_rn(px[i], bx);
            float dy = __fsub_rn(py[i], by);
            float dz = __fsub_rn(pz[i], bz);
            float d = __fadd_rn(__fadd_rn(__fmul_rn(dx,dx), __fmul_rn(dy,dy)), __fmul_rn(dz,dz));
            float nd = fminf(dist[i], d);
            dist[i] = nd;
            int p = tid + i*512;
            if (nd > bestv || (nd == bestv && p < besti)) { bestv = nd; besti = p; }
        }
        #pragma unroll
        for (int off = 16; off; off >>= 1) {
            float ov = __shfl_down_sync(0xffffffffu, bestv, off);
            int   oi = __shfl_down_sync(0xffffffffu, besti, off);
            if (ov > bestv || (ov == bestv && oi < besti)) { bestv = ov; besti = oi; }
        }
        if ((tid & 31) == 0) { swv[tid>>5] = bestv; swi[tid>>5] = besti; }
        __syncthreads();
        if (tid == 0) {
            float v = swv[0]; int ii = swi[0];
            #pragma unroll
            for (int w = 1; w < 16; w++)
                if (swv[w] > v || (swv[w] == v && swi[w] < ii)) { v = swv[w]; ii = swi[w]; }
            float x0 = P[ii*3+0], y0 = P[ii*3+1], z0 = P[ii*3+2];
            sbx = x0; sby = y0; sbz = z0;
            anch[s*3+0] = x0; anch[s*3+1] = y0; anch[s*3+2] = z0;
        }
        __syncthreads();
    }
}

// ---------------- Ball query ------------------------------------------------
__global__ __launch_bounds__(128) void ball_kernel(const float* __restrict__ xyzs) {
    int w = blockIdx.x*4 + (threadIdx.x >> 5);
    int lane = threadIdx.x & 31;
    int o = w / NTOK;
    int tok = w % NTOK;
    int b = tok / LTOK, loc = tok % LTOK, j = loc / MM;
    int pf = 2*j + o;
    int of = (pf == 0) ? 0 : (pf - 1);
    const float* P = xyzs + (size_t)(b*NT + of)*NP*3;
    float ax = g_anchor[tok*3+0], ay = g_anchor[tok*3+1], az = g_anchor[tok*3+2];
    int* out = g_ball + ((size_t)o*NTOK + tok)*KSAMP;
    int cnt = 0, first = 0; bool found = false;
    for (int base = 0; base < NP; base += 32) {
        int p = base + lane;
        float x = P[p*3+0], y = P[p*3+1], z = P[p*3+2];
        float dx = __fsub_rn(ax,x), dy = __fsub_rn(ay,y), dz = __fsub_rn(az,z);
        float d2 = __fadd_rn(__fadd_rn(__fmul_rn(dx,dx), __fmul_rn(dy,dy)), __fmul_rn(dz,dz));
        bool inside = d2 < RAD2;
        unsigned msk = __ballot_sync(0xffffffffu, inside);
        if (!found && msk) { first = base + __ffs(msk) - 1; found = true; }
        int pos = cnt + __popc(msk & ((1u << lane) - 1u));
        if (inside && pos < KSAMP) out[pos] = p;
        cnt += __popc(msk);
        if (cnt >= KSAMP) break;
    }
    if (lane >= cnt) out[lane] = found ? first : 0;
}

// ---------------- grouped conv: one block per (token, o); partial max ------
__global__ __launch_bounds__(128) void conv_kernel(
    const float* __restrict__ xyzs, const float* __restrict__ oldf,
    const float* __restrict__ Wd, const float* __restrict__ Wf)
{
    int tok = blockIdx.x;
    int o = blockIdx.y;
    int b = tok / LTOK, loc = tok % LTOK, j = loc / MM;
    int tid = threadIdx.x;
    __shared__ float sd[KSAMP][4];
    __shared__ float sf[KSAMP][2];
    float ax = g_anchor[tok*3+0], ay = g_anchor[tok*3+1], az = g_anchor[tok*3+2];

    float wd[4][4], wf[4][2], vmax[4];
    #pragma unroll
    for (int r = 0; r < 4; r++) {
        int d = tid + 128*r;
        wd[r][0] = Wd[d*4+0]; wd[r][1] = Wd[d*4+1]; wd[r][2] = Wd[d*4+2]; wd[r][3] = Wd[d*4+3];
        wf[r][0] = Wf[d*2+0]; wf[r][1] = Wf[d*2+1];
        vmax[r] = -3.402823466e38f;
    }
    int pf = 2*j + o;
    int of = (pf == 0) ? 0 : (pf - 1);
    const float* P = xyzs + (size_t)(b*NT + of)*NP*3;
    const float* F = oldf + (size_t)(b*NT + of)*2*NP;
    if (tid < KSAMP) {
        int idx = g_ball[((size_t)o*NTOK + tok)*KSAMP + tid];
        sd[tid][0] = P[idx*3+0] - ax;
        sd[tid][1] = P[idx*3+1] - ay;
        sd[tid][2] = P[idx*3+2] - az;
        sd[tid][3] = (float)(o - 1);
        sf[tid][0] = F[idx];
        sf[tid][1] = F[NP + idx];
    }
    __syncthreads();
    #pragma unroll 4
    for (int k = 0; k < KSAMP; k++) {
        float d0 = sd[k][0], d1 = sd[k][1], d2 = sd[k][2], d3 = sd[k][3];
        float f0 = sf[k][0], f1 = sf[k][1];
        #pragma unroll
        for (int r = 0; r < 4; r++) {
            float de = wd[r][0]*d0 + wd[r][1]*d1 + wd[r][2]*d2 + wd[r][3]*d3;
            float fe = wf[r][0]*f0 + wf[r][1]*f1;
            vmax[r] = fmaxf(vmax[r], de*fe);
        }
    }
    #pragma unroll
    for (int r = 0; r < 4; r++)
        g_featp[((size_t)o*NTOK + tok)*EDIM + tid + 128*r] = vmax[r];
}

// ---------------- pos + contrastive + 3-way feat max + relu ----------------
__global__ __launch_bounds__(512) void embed_kernel(
    const float* __restrict__ pw, const float* __restrict__ pb,
    const float* __restrict__ cw, const float* __restrict__ cb,
    float* __restrict__ dout)
{
    int tok = blockIdx.x;
    int d = threadIdx.x;
    int loc = tok % LTOK, j = loc / MM;
    float ax = g_anchor[tok*3+0], ay = g_anchor[tok*3+1], az = g_anchor[tok*3+2];
    float tv = (float)(j + 1);
    float pos = pw[d*4+0]*ax + pw[d*4+1]*ay + pw[d*4+2]*az + pw[d*4+3]*tv + pb[d];
    float con = cw[d*4+0]*ax + cw[d*4+1]*ay + cw[d*4+2]*az + cw[d*4+3]*tv + cb[d];
    dout[CONTR_OFF + (size_t)tok*EDIM + d] = con;
    size_t fo = (size_t)tok*EDIM + d;
    float feat = fmaxf(fmaxf(g_featp[fo], g_featp[(size_t)NTOK*EDIM + fo]),
                       g_featp[2*(size_t)NTOK*EDIM + fo]);
    dout[FEAT_OFF + fo] = feat;
    g_x[fo] = fmaxf(pos + feat, 0.0f);
}

// ---------------- LayerNorm -> bf16 hi/lo ----------------------------------
__global__ __launch_bounds__(256) void ln_split_kernel(
    const float* __restrict__ x, const float* __restrict__ s,
    const float* __restrict__ bb,
    __nv_bfloat16* __restrict__ outh, __nv_bfloat16* __restrict__ outl)
{
    int tok = blockIdx.x;
    int tid = threadIdx.x;
    const float* row = x + (size_t)tok*EDIM;
    float v0 = row[tid], v1 = row[tid + 256];
    float sum = v0 + v1, sq = v0*v0 + v1*v1;
    #pragma unroll
    for (int off = 16; off; off >>= 1) {
        sum += __shfl_xor_sync(0xffffffffu, sum, off);
        sq  += __shfl_xor_sync(0xffffffffu, sq, off);
    }
    __shared__ float ssum[8], ssq[8];
    if ((tid & 31) == 0) { ssum[tid>>5] = sum; ssq[tid>>5] = sq; }
    __syncthreads();
    float ts = 0.f, tq = 0.f;
    #pragma unroll
    for (int w = 0; w < 8; w++) { ts += ssum[w]; tq += ssq[w]; }
    float mu = ts * (1.0f/512.0f);
    float var = tq * (1.0f/512.0f) - mu*mu;
    float rstd = rsqrtf(var + 1e-5f);
    float y0 = (v0 - mu)*rstd*s[tid] + bb[tid];
    float y1 = (v1 - mu)*rstd*s[tid+256] + bb[tid+256];
    __nv_bfloat16 h0 = __float2bfloat16(y0);
    __nv_bfloat16 h1 = __float2bfloat16(y1);
    outh[(size_t)tok*EDIM + tid]       = h0;
    outh[(size_t)tok*EDIM + tid + 256] = h1;
    outl[(size_t)tok*EDIM + tid]       = __float2bfloat16(y0 - __bfloat162float(h0));
    outl[(size_t)tok*EDIM + tid + 256] = __float2bfloat16(y1 - __bfloat162float(h1));
}

// ---------------- fp32 LayerNorm (head) ------------------------------------
__global__ __launch_bounds__(256) void ln_kernel(
    const float* __restrict__ x, const float* __restrict__ s,
    const float* __restrict__ bb, float* __restrict__ out)
{
    int tok = blockIdx.x;
    int tid = threadIdx.x;
    const float* row = x + (size_t)tok*EDIM;
    float v0 = row[tid], v1 = row[tid + 256];
    float sum = v0 + v1, sq = v0*v0 + v1*v1;
    #pragma unroll
    for (int off = 16; off; off >>= 1) {
        sum += __shfl_xor_sync(0xffffffffu, sum, off);
        sq  += __shfl_xor_sync(0xffffffffu, sq, off);
    }
    __shared__ float ssum[8], ssq[8];
    if ((tid & 31) == 0) { ssum[tid>>5] = sum; ssq[tid>>5] = sq; }
    __syncthreads();
    float ts = 0.f, tq = 0.f;
    #pragma unroll
    for (int w = 0; w < 8; w++) { ts += ssum[w]; tq += ssq[w]; }
    float mu = ts * (1.0f/512.0f);
    float var = tq * (1.0f/512.0f) - mu*mu;
    float rstd = rsqrtf(var + 1e-5f);
    out[(size_t)tok*EDIM + tid]       = (v0 - mu)*rstd*s[tid] + bb[tid];
    out[(size_t)tok*EDIM + tid + 256] = (v1 - mu)*rstd*s[tid+256] + bb[tid+256];
}

// ---------------- head ------------------------------------------------------
__global__ __launch_bounds__(512) void pool1_kernel() {
    int chunk = blockIdx.x, b = blockIdx.y;
    int d = threadIdx.x;
    float v = -3.402823466e38f;
    const float* p = g_x + ((size_t)b*LTOK + chunk*128)*EDIM + d;
    #pragma unroll 4
    for (int i = 0; i < 128; i++) v = fmaxf(v, p[(size_t)i*EDIM]);
    g_poolp[((size_t)b*12 + chunk)*EDIM + d] = v;
}
__global__ __launch_bounds__(512) void pool2_kernel() {
    int b = blockIdx.x;
    int d = threadIdx.x;
    float v = -3.402823466e38f;
    #pragma unroll
    for (int c = 0; c < 12; c++) v = fmaxf(v, g_poolp[((size_t)b*12 + c)*EDIM + d]);
    g_pool[b*EDIM + d] = v;
}
__global__ __launch_bounds__(256) void head1_kernel(
    const float* __restrict__ W, const float* __restrict__ bias)
{
    int out = blockIdx.x*8 + (threadIdx.x >> 5);
    int lane = threadIdx.x & 31;
    int b = out >> 10, jj = out & 1023;
    const float* xr = g_hln + b*EDIM;
    const float* wr = W + (size_t)jj*EDIM;
    float s = 0.f;
    for (int d = lane; d < EDIM; d += 32) s += xr[d]*wr[d];
    #pragma unroll
    for (int off = 16; off; off >>= 1) s += __shfl_xor_sync(0xffffffffu, s, off);
    if (lane == 0) g_h1[out] = gelu_exact(s + bias[jj]);
}
__global__ __launch_bounds__(128) void head2_kernel(
    const float* __restrict__ W, const float* __restrict__ bias,
    float* __restrict__ dout)
{
    int out = blockIdx.x*4 + (threadIdx.x >> 5);
    int lane = threadIdx.x & 31;
    int b = out / NCLS, c = out % NCLS;
    float s = 0.f;
    for (int d = lane; d < MLPD; d += 32) s += g_h1[b*MLPD + d]*W[(size_t)c*MLPD + d];
    #pragma unroll
    for (int off = 16; off; off >>= 1) s += __shfl_xor_sync(0xffffffffu, s, off);
    if (lane == 0) dout[out] = s + bias[c];
}

// ---------------- launch ---------------------------------------------------
extern "C" void kernel_launch(void* const* d_in, const int* in_sizes, int n_in,
                              void* d_out, int out_size) {
    const float* xyzs      = (const float*)d_in[0];
    const float* oldf      = (const float*)d_in[1];
    const float* conv_d_w  = (const float*)d_in[2];
    const float* conv_f_w  = (const float*)d_in[3];
    const float* pos_w     = (const float*)d_in[4];
    const float* pos_b     = (const float*)d_in[5];
    const float* contr_w   = (const float*)d_in[6];
    const float* contr_b   = (const float*)d_in[7];
    const float* ln1_s     = (const float*)d_in[8];
    const float* ln1_b     = (const float*)d_in[9];
    const float* qkv_w     = (const float*)d_in[10];
    const float* out_w     = (const float*)d_in[11];
    const float* out_b     = (const float*)d_in[12];
    const float* ln2_s     = (const float*)d_in[13];
    const float* ln2_b     = (const float*)d_in[14];
    const float* ff1_w     = (const float*)d_in[15];
    const float* ff1_b     = (const float*)d_in[16];
    const float* ff2_w     = (const float*)d_in[17];
    const float* ff2_b     = (const float*)d_in[18];
    const float* head_ln_s = (const float*)d_in[19];
    const float* head_ln_b = (const float*)d_in[20];
    const float* head1_w   = (const float*)d_in[21];
    const float* head1_b   = (const float*)d_in[22];
    const float* head2_w   = (const float*)d_in[23];
    const float* head2_b   = (const float*)d_in[24];
    float* out = (float*)d_out;

    float *px, *ppool, *phln;
    __nv_bfloat16 *pwh, *pwl, *phh, *phl, *pqh, *pql, *poh, *pol, *pf1h, *pf1l;
    cudaGetSymbolAddress((void**)&px,    g_x);
    cudaGetSymbolAddress((void**)&ppool, g_pool);
    cudaGetSymbolAddress((void**)&phln,  g_hln);
    cudaGetSymbolAddress((void**)&pwh,   g_wh);
    cudaGetSymbolAddress((void**)&pwl,   g_wl);
    cudaGetSymbolAddress((void**)&phh,   g_hh);
    cudaGetSymbolAddress((void**)&phl,   g_hl);
    cudaGetSymbolAddress((void**)&pqh,   g_qh);
    cudaGetSymbolAddress((void**)&pql,   g_ql);
    cudaGetSymbolAddress((void**)&poh,   g_oh);
    cudaGetSymbolAddress((void**)&pol,   g_ol);
    cudaGetSymbolAddress((void**)&pf1h,  g_f1h);
    cudaGetSymbolAddress((void**)&pf1l,  g_f1l);

    cudaFuncSetAttribute(flash_kernel, cudaFuncAttributeMaxDynamicSharedMemorySize, FA_SMEM);
    cudaFuncSetAttribute(tgemm_b, cudaFuncAttributeMaxDynamicSharedMemorySize, G_SMEM);
    cudaFuncSetAttribute(tgemm_b64, cudaFuncAttributeMaxDynamicSharedMemorySize, G64_SMEM);

    // ---- one-time weight split (single fused launch; graph-safe) ----
    wsplit_all_kernel<<<WTOT/1024, 256>>>(qkv_w, out_w, ff1_w, ff2_w, pwh, pwl);

    fps_kernel<<<48, 512>>>(xyzs);
    ball_kernel<<<(3*NTOK)/4, 128>>>(xyzs);
    conv_kernel<<<dim3(NTOK, 3), 128>>>(xyzs, oldf, conv_d_w, conv_f_w);
    embed_kernel<<<NTOK, 512>>>(pos_w, pos_b, contr_w, contr_b, out);

    for (int l = 0; l < 4; l++) {
        ln_split_kernel<<<NTOK, 256>>>(px, ln1_s + l*EDIM, ln1_b + l*EDIM, phh, phl);
        // QKV: split output (Q pre-scaled by 1/8)
        tgemm_b<<<dim3(12,48,1), 256, G_SMEM>>>(
            phh, phl, pwh + WQKV_OFF + (size_t)l*1536*512, pwl + WQKV_OFF + (size_t)l*1536*512,
            nullptr, nullptr, pqh, pql,
            512, 512, 512, 1536, 0,0,0, 1,1);
        // fused attention -> o hi/lo
        flash_kernel<<<dim3(LTOK/128, NB*NHEAD), 256, FA_SMEM>>>(pqh, pql, poh, pol);
        // out proj + residual (fp32 out) — BN=64
        tgemm_b64<<<dim3(8,48,1), 256, G64_SMEM>>>(
            poh, pol, pwh + WOUT_OFF + (size_t)l*512*512, pwl + WOUT_OFF + (size_t)l*512*512,
            out_b + l*EDIM, px, nullptr, nullptr,
            512, 512, 512, 512, 0,1,1, 0);
        ln_split_kernel<<<NTOK, 256>>>(px, ln2_s + l*EDIM, ln2_b + l*EDIM, phh, phl);
        // ff1 + gelu: split output — BN=64
        tgemm_b64<<<dim3(16,48,1), 256, G64_SMEM>>>(
            phh, phl, pwh + WFF1_OFF + (size_t)l*1024*512, pwl + WFF1_OFF + (size_t)l*1024*512,
            ff1_b + l*MLPD, nullptr, pf1h, pf1l,
            512, 512, 512, 1024, 1,0,1, 1);
        // ff2 + residual (fp32 out) — BN=64
        tgemm_b64<<<dim3(8,48,1), 256, G64_SMEM>>>(
            pf1h, pf1l, pwh + WFF2_OFF + (size_t)l*512*1024, pwl + WFF2_OFF + (size_t)l*512*1024,
            ff2_b + l*EDIM, px, nullptr, nullptr,
            1024, 1024, 1024, 512, 0,1,1, 0);
    }

    pool1_kernel<<<dim3(12, NB), 512>>>();
    pool2_kernel<<<NB, 512>>>();
    ln_kernel<<<NB, 256>>>(ppool, head_ln_s, head_ln_b, phln);
    head1_kernel<<<(NB*MLPD)/8, 256>>>(head1_w, head1_b);
    head2_kernel<<<NB*NCLS/4, 128>>>(head2_w, head2_b, out);
}

// round 12
// speedup vs baseline: 1.0099x; 1.0099x over previous
#include <cuda_runtime.h>
#include <cuda_bf16.h>
#include <cstdint>
#include <math.h>

#define NB 4
#define NT 24
#define NP 4096
#define MM 128
#define TO 12
#define LTOK 1536
#define NTOK 6144
#define EDIM 512
#define NHEAD 8
#define DHEAD 64
#define MLPD 1024
#define NCLS 30
#define KSAMP 32
#define RAD2 0.09f

#define CONTR_OFF 120
#define FEAT_OFF (120 + NTOK*EDIM)

// weight-split buffer offsets (elements)
#define WQKV_OFF 0
#define WOUT_OFF 3145728
#define WFF1_OFF 4194304
#define WFF2_OFF 6291456
#define WTOT     8388608

// ---------------- scratch (device globals; no cudaMalloc allowed) ----------
__device__ __align__(256) float g_anchor[NTOK*3];
__device__ __align__(256) int   g_ball[3*NTOK*KSAMP];
__device__ __align__(256) float g_x[NTOK*EDIM];
__device__ __align__(256) float g_pool[NB*EDIM];
__device__ __align__(256) float g_poolp[NB*12*EDIM];
__device__ __align__(256) float g_hln[NB*EDIM];
__device__ __align__(256) float g_h1[NB*MLPD];

__device__ __align__(256) __nv_bfloat16 g_wh[WTOT];
__device__ __align__(256) __nv_bfloat16 g_wl[WTOT];
__device__ __align__(256) __nv_bfloat16 g_hh[NTOK*EDIM];
__device__ __align__(256) __nv_bfloat16 g_hl[NTOK*EDIM];
__device__ __align__(256) __nv_bfloat16 g_qh[NTOK*1536];
__device__ __align__(256) __nv_bfloat16 g_ql[NTOK*1536];
__device__ __align__(256) __nv_bfloat16 g_oh[NTOK*EDIM];
__device__ __align__(256) __nv_bfloat16 g_ol[NTOK*EDIM];
__device__ __align__(256) __nv_bfloat16 g_f1h[NTOK*MLPD];
__device__ __align__(256) __nv_bfloat16 g_f1l[NTOK*MLPD];

__device__ __forceinline__ float gelu_exact(float x){
    return 0.5f*x*(1.0f+erff(x*0.70710678118654752440f));
}

// ==================== PTX helpers ==========================================
__device__ __forceinline__ void mma16816(float* c, const unsigned* a, const unsigned* b){
    asm volatile("mma.sync.aligned.m16n8k16.row.col.f32.bf16.bf16.f32 "
        "{%0,%1,%2,%3}, {%4,%5,%6,%7}, {%8,%9}, {%0,%1,%2,%3};"
        : "+f"(c[0]),"+f"(c[1]),"+f"(c[2]),"+f"(c[3])
        : "r"(a[0]),"r"(a[1]),"r"(a[2]),"r"(a[3]), "r"(b[0]),"r"(b[1]));
}
__device__ __forceinline__ void split2(float x, float y, unsigned& hi, unsigned& lo){
    __nv_bfloat16 hx = __float2bfloat16(x), hy = __float2bfloat16(y);
    float rx = x - __bfloat162float(hx), ry = y - __bfloat162float(hy);
    __nv_bfloat16 lx = __float2bfloat16(rx), ly = __float2bfloat16(ry);
    hi = (unsigned)__bfloat16_as_ushort(hx) | ((unsigned)__bfloat16_as_ushort(hy) << 16);
    lo = (unsigned)__bfloat16_as_ushort(lx) | ((unsigned)__bfloat16_as_ushort(ly) << 16);
}
__device__ __forceinline__ unsigned smem_u32(const void* p){
    unsigned a;
    asm("{ .reg .u64 t; cvta.to.shared.u64 t, %1; cvt.u32.u64 %0, t; }" : "=r"(a) : "l"(p));
    return a;
}
__device__ __forceinline__ void ldmx4(unsigned* r, unsigned addr){
    asm volatile("ldmatrix.sync.aligned.m8n8.x4.shared.b16 {%0,%1,%2,%3}, [%4];"
        : "=r"(r[0]),"=r"(r[1]),"=r"(r[2]),"=r"(r[3]) : "r"(addr));
}
__device__ __forceinline__ void ldmx4t(unsigned* r, unsigned addr){
    asm volatile("ldmatrix.sync.aligned.m8n8.x4.trans.shared.b16 {%0,%1,%2,%3}, [%4];"
        : "=r"(r[0]),"=r"(r[1]),"=r"(r[2]),"=r"(r[3]) : "r"(addr));
}
#define CP16(d, s) asm volatile("cp.async.cg.shared.global [%0], [%1], 16;" :: "r"(d), "l"(s) : "memory")
#define CPC() asm volatile("cp.async.commit_group;" ::: "memory")
#define CPW0() asm volatile("cp.async.wait_group 0;" ::: "memory")

// ---------------- fused weight split prep (single launch) -------------------
__global__ __launch_bounds__(256) void wsplit_all_kernel(
    const float* __restrict__ qkv_w, const float* __restrict__ out_w,
    const float* __restrict__ ff1_w, const float* __restrict__ ff2_w,
    __nv_bfloat16* __restrict__ hi, __nv_bfloat16* __restrict__ lo)
{
    int i = (blockIdx.x*256 + threadIdx.x)*4;
    if (i >= WTOT) return;
    const float* src;
    int off;
    if (i < WOUT_OFF)       { src = qkv_w; off = i - WQKV_OFF; }
    else if (i < WFF1_OFF)  { src = out_w; off = i - WOUT_OFF; }
    else if (i < WFF2_OFF)  { src = ff1_w; off = i - WFF1_OFF; }
    else                    { src = ff2_w; off = i - WFF2_OFF; }
    float4 v = *(const float4*)(src + off);
    unsigned h0, l0, h1, l1;
    split2(v.x, v.y, h0, l0); split2(v.z, v.w, h1, l1);
    *(unsigned*)(hi+i) = h0; *(unsigned*)(hi+i+2) = h1;
    *(unsigned*)(lo+i) = l0; *(unsigned*)(lo+i+2) = l1;
}

#define LDT 40                       // smem row stride in bf16 (32 + 8 pad)
#define GARR (128*LDT*2)             // 10240 B per 128-row array
#define GSTAGE (4*GARR)              // 40960 B per stage
#define G_SMEM (2*GSTAGE)            // 81920 B

// ============ GEMM BN=128, pre-split bf16, cp.async, ldmatrix ==============
__global__ __launch_bounds__(256) void tgemm_b(
    const __nv_bfloat16* __restrict__ AH_, const __nv_bfloat16* __restrict__ AL_,
    const __nv_bfloat16* __restrict__ WH_, const __nv_bfloat16* __restrict__ WL_,
    const float* __restrict__ bias, float* __restrict__ Cf,
    __nv_bfloat16* __restrict__ CH_, __nv_bfloat16* __restrict__ CL_,
    int K, int lda, int ldw, int ldc,
    int act, int resid, int hasb, int split, int qscale)
{
    extern __shared__ char smem[];
    unsigned sb = smem_u32(smem);

    int tid = threadIdx.x, wid = tid >> 5, lane = tid & 31;
    int g = lane >> 2, tg = lane & 3;
    int q8 = lane >> 3, lr8 = lane & 7;
    int rw = (wid >> 2) * 64, cw = (wid & 3) * 32;
    int bm = blockIdx.y * 128, bn = blockIdx.x * 128;

    float acc[4][4][4];
    #pragma unroll
    for (int i = 0; i < 4; i++)
        #pragma unroll
        for (int j = 0; j < 4; j++)
            #pragma unroll
            for (int p = 0; p < 4; p++) acc[i][j][p] = 0.f;

    int row = tid >> 1, half = tid & 1;
    int nch = K >> 5;

    {
        unsigned dst = sb + (row*LDT + half*16)*2;
        const __nv_bfloat16* a = AH_ + (size_t)(bm+row)*lda + half*16;
        const __nv_bfloat16* a2 = AL_ + (size_t)(bm+row)*lda + half*16;
        const __nv_bfloat16* w = WH_ + (size_t)(bn+row)*ldw + half*16;
        const __nv_bfloat16* w2 = WL_ + (size_t)(bn+row)*ldw + half*16;
        CP16(dst, a); CP16(dst+16, a+8);
        CP16(dst+GARR, a2); CP16(dst+GARR+16, a2+8);
        CP16(dst+2*GARR, w); CP16(dst+2*GARR+16, w+8);
        CP16(dst+3*GARR, w2); CP16(dst+3*GARR+16, w2+8);
        CPC();
    }

    for (int c = 0; c < nch; c++) {
        CPW0();
        __syncthreads();
        if (c + 1 < nch) {
            unsigned dst = sb + ((c+1)&1)*GSTAGE + (row*LDT + half*16)*2;
            const __nv_bfloat16* a = AH_ + (size_t)(bm+row)*lda + (c+1)*32 + half*16;
            const __nv_bfloat16* a2 = AL_ + (size_t)(bm+row)*lda + (c+1)*32 + half*16;
            const __nv_bfloat16* w = WH_ + (size_t)(bn+row)*ldw + (c+1)*32 + half*16;
            const __nv_bfloat16* w2 = WL_ + (size_t)(bn+row)*ldw + (c+1)*32 + half*16;
            CP16(dst, a); CP16(dst+16, a+8);
            CP16(dst+GARR, a2); CP16(dst+GARR+16, a2+8);
            CP16(dst+2*GARR, w); CP16(dst+2*GARR+16, w+8);
            CP16(dst+3*GARR, w2); CP16(dst+3*GARR+16, w2+8);
            CPC();
        }
        unsigned sAH = sb + (c&1)*GSTAGE;
        unsigned sAL = sAH + GARR;
        unsigned sWH = sAH + 2*GARR;
        unsigned sWL = sAH + 3*GARR;
        #pragma unroll
        for (int ks = 0; ks < 2; ks++) {
            int k0 = ks * 16;
            unsigned ah[4][4], al[4][4], bh[2][4], bl[2][4];
            #pragma unroll
            for (int mt = 0; mt < 4; mt++) {
                unsigned off = (unsigned)((rw + mt*16 + (q8&1)*8 + lr8)*LDT + k0 + (q8>>1)*8)*2;
                ldmx4(ah[mt], sAH + off);
                ldmx4(al[mt], sAL + off);
            }
            #pragma unroll
            for (int ntp = 0; ntp < 2; ntp++) {
                unsigned off = (unsigned)((cw + ntp*16 + (q8>>1)*8 + lr8)*LDT + k0 + (q8&1)*8)*2;
                ldmx4(bh[ntp], sWH + off);
                ldmx4(bl[ntp], sWL + off);
            }
            #pragma unroll
            for (int mt = 0; mt < 4; mt++)
                #pragma unroll
                for (int nt = 0; nt < 4; nt++) {
                    const unsigned* ph = &bh[nt>>1][(nt&1)*2];
                    const unsigned* pl = &bl[nt>>1][(nt&1)*2];
                    mma16816(acc[mt][nt], ah[mt], ph);
                    mma16816(acc[mt][nt], ah[mt], pl);
                    mma16816(acc[mt][nt], al[mt], ph);
                }
        }
    }
    #pragma unroll
    for (int mt = 0; mt < 4; mt++) {
        #pragma unroll
        for (int nt = 0; nt < 4; nt++) {
            int r0 = bm + rw + mt*16 + g;
            int col = bn + cw + nt*8 + tg*2;
            #pragma unroll
            for (int half2 = 0; half2 < 2; half2++) {
                int r = r0 + half2*8;
                float v0 = acc[mt][nt][half2*2+0];
                float v1 = acc[mt][nt][half2*2+1];
                if (hasb) { v0 += bias[col]; v1 += bias[col+1]; }
                if (act)  { v0 = gelu_exact(v0); v1 = gelu_exact(v1); }
                if (split) {
                    if (qscale && col < 512) { v0 *= 0.125f; v1 *= 0.125f; }
                    unsigned hh, ll;
                    split2(v0, v1, hh, ll);
                    *(unsigned*)(CH_ + (size_t)r*ldc + col) = hh;
                    *(unsigned*)(CL_ + (size_t)r*ldc + col) = ll;
                } else {
                    float* cp = Cf + (size_t)r * ldc + col;
                    if (resid) {
                        float2 old = *(float2*)cp;
                        v0 += old.x; v1 += old.y;
                    }
                    float2 ov = {v0, v1};
                    *(float2*)cp = ov;
                }
            }
        }
    }
}

// ============ GEMM BN=64 (wave fill for narrow N) ==========================
#define G64_WARR (64*LDT*2)              // 5120 B
#define G64_STAGE (2*GARR + 2*G64_WARR)  // 30720 B
#define G64_SMEM (2*G64_STAGE)           // 61440 B

__global__ __launch_bounds__(256) void tgemm_b64(
    const __nv_bfloat16* __restrict__ AH_, const __nv_bfloat16* __restrict__ AL_,
    const __nv_bfloat16* __restrict__ WH_, const __nv_bfloat16* __restrict__ WL_,
    const float* __restrict__ bias, float* __restrict__ Cf,
    __nv_bfloat16* __restrict__ CH_, __nv_bfloat16* __restrict__ CL_,
    int K, int lda, int ldw, int ldc,
    int act, int resid, int hasb, int split)
{
    extern __shared__ char smem[];
    unsigned sb = smem_u32(smem);

    int tid = threadIdx.x, wid = tid >> 5, lane = tid & 31;
    int g = lane >> 2, tg = lane & 3;
    int q8 = lane >> 3, lr8 = lane & 7;
    int rw = (wid >> 2) * 64, cw = (wid & 3) * 16;
    int bm = blockIdx.y * 128, bn = blockIdx.x * 64;

    float acc[4][2][4];
    #pragma unroll
    for (int i = 0; i < 4; i++)
        #pragma unroll
        for (int j = 0; j < 2; j++)
            #pragma unroll
            for (int p = 0; p < 4; p++) acc[i][j][p] = 0.f;

    int row = tid >> 1, half = tid & 1;
    int roww = tid >> 2, colq = (tid & 3) * 8;
    int nch = K >> 5;

    {
        unsigned dstA = sb + (row*LDT + half*16)*2;
        const __nv_bfloat16* a = AH_ + (size_t)(bm+row)*lda + half*16;
        const __nv_bfloat16* a2 = AL_ + (size_t)(bm+row)*lda + half*16;
        CP16(dstA, a); CP16(dstA+16, a+8);
        CP16(dstA+GARR, a2); CP16(dstA+GARR+16, a2+8);
        unsigned dstW = sb + 2*GARR + (roww*LDT + colq)*2;
        const __nv_bfloat16* w = WH_ + (size_t)(bn+roww)*ldw + colq;
        const __nv_bfloat16* w2 = WL_ + (size_t)(bn+roww)*ldw + colq;
        CP16(dstW, w);
        CP16(dstW+G64_WARR, w2);
        CPC();
    }

    for (int c = 0; c < nch; c++) {
        CPW0();
        __syncthreads();
        if (c + 1 < nch) {
            unsigned st = ((c+1)&1)*G64_STAGE;
            unsigned dstA = sb + st + (row*LDT + half*16)*2;
            const __nv_bfloat16* a = AH_ + (size_t)(bm+row)*lda + (c+1)*32 + half*16;
            const __nv_bfloat16* a2 = AL_ + (size_t)(bm+row)*lda + (c+1)*32 + half*16;
            CP16(dstA, a); CP16(dstA+16, a+8);
            CP16(dstA+GARR, a2); CP16(dstA+GARR+16, a2+8);
            unsigned dstW = sb + st + 2*GARR + (roww*LDT + colq)*2;
            const __nv_bfloat16* w = WH_ + (size_t)(bn+roww)*ldw + (c+1)*32 + colq;
            const __nv_bfloat16* w2 = WL_ + (size_t)(bn+roww)*ldw + (c+1)*32 + colq;
            CP16(dstW, w);
            CP16(dstW+G64_WARR, w2);
            CPC();
        }
        unsigned sAH = sb + (c&1)*G64_STAGE;
        unsigned sAL = sAH + GARR;
        unsigned sWH = sAH + 2*GARR;
        unsigned sWL = sWH + G64_WARR;
        #pragma unroll
        for (int ks = 0; ks < 2; ks++) {
            int k0 = ks * 16;
            unsigned ah[4][4], al[4][4], bh4[4], bl4[4];
            #pragma unroll
            for (int mt = 0; mt < 4; mt++) {
                unsigned off = (unsigned)((rw + mt*16 + (q8&1)*8 + lr8)*LDT + k0 + (q8>>1)*8)*2;
                ldmx4(ah[mt], sAH + off);
                ldmx4(al[mt], sAL + off);
            }
            {
                unsigned off = (unsigned)((cw + (q8>>1)*8 + lr8)*LDT + k0 + (q8&1)*8)*2;
                ldmx4(bh4, sWH + off);
                ldmx4(bl4, sWL + off);
            }
            #pragma unroll
            for (int mt = 0; mt < 4; mt++)
                #pragma unroll
                for (int nt = 0; nt < 2; nt++) {
                    mma16816(acc[mt][nt], ah[mt], bh4 + nt*2);
                    mma16816(acc[mt][nt], ah[mt], bl4 + nt*2);
                    mma16816(acc[mt][nt], al[mt], bh4 + nt*2);
                }
        }
    }
    #pragma unroll
    for (int mt = 0; mt < 4; mt++) {
        #pragma unroll
        for (int nt = 0; nt < 2; nt++) {
            int r0 = bm + rw + mt*16 + g;
            int col = bn + cw + nt*8 + tg*2;
            #pragma unroll
            for (int half2 = 0; half2 < 2; half2++) {
                int r = r0 + half2*8;
                float v0 = acc[mt][nt][half2*2+0];
                float v1 = acc[mt][nt][half2*2+1];
                if (hasb) { v0 += bias[col]; v1 += bias[col+1]; }
                if (act)  { v0 = gelu_exact(v0); v1 = gelu_exact(v1); }
                if (split) {
                    unsigned hh, ll;
                    split2(v0, v1, hh, ll);
                    *(unsigned*)(CH_ + (size_t)r*ldc + col) = hh;
                    *(unsigned*)(CL_ + (size_t)r*ldc + col) = ll;
                } else {
                    float* cp = Cf + (size_t)r * ldc + col;
                    if (resid) {
                        float2 old = *(float2*)cp;
                        v0 += old.x; v1 += old.y;
                    }
                    float2 ov = {v0, v1};
                    *(float2*)cp = ov;
                }
            }
        }
    }
}

// ==================== flash attention ======================================
#define FQS 72
#define FARR (128*FQS*2)             // 18432 B
#define FQH 0
#define FQL FARR
#define FST(s) (2*FARR + (s)*4*FARR)
#define FA_SMEM (2*FARR + 2*4*FARR)  // 184320 B

__global__ __launch_bounds__(256) void flash_kernel(
    const __nv_bfloat16* __restrict__ qh, const __nv_bfloat16* __restrict__ ql,
    __nv_bfloat16* __restrict__ oh, __nv_bfloat16* __restrict__ ol)
{
    extern __shared__ char fsm[];
    unsigned sb = smem_u32(fsm);

    int tid = threadIdx.x, wid = tid >> 5, lane = tid & 31;
    int g = lane >> 2, tg = lane & 3;
    int q8 = lane >> 3, lr8 = lane & 7;
    int z = blockIdx.y;
    int b = z >> 3, h = z & 7;
    size_t base = (size_t)b * LTOK * 1536;
    int q0 = blockIdx.x * 128;

    int row = tid >> 1, half = tid & 1;

    {
        unsigned dq = sb + (row*FQS + half*32)*2;
        const __nv_bfloat16* sq = qh + base + (size_t)(q0+row)*1536 + h*64 + half*32;
        const __nv_bfloat16* sq2 = ql + base + (size_t)(q0+row)*1536 + h*64 + half*32;
        #pragma unroll
        for (int j = 0; j < 4; j++) {
            CP16(dq + j*16, sq + j*8);
            CP16(dq + FARR + j*16, sq2 + j*8);
        }
        unsigned dk = sb + FST(0) + (row*FQS + half*32)*2;
        const __nv_bfloat16* sk = qh + base + (size_t)row*1536 + 512 + h*64 + half*32;
        const __nv_bfloat16* sk2 = ql + base + (size_t)row*1536 + 512 + h*64 + half*32;
        const __nv_bfloat16* sv = qh + base + (size_t)row*1536 + 1024 + h*64 + half*32;
        const __nv_bfloat16* sv2 = ql + base + (size_t)row*1536 + 1024 + h*64 + half*32;
        #pragma unroll
        for (int j = 0; j < 4; j++) {
            CP16(dk + j*16, sk + j*8);
            CP16(dk + FARR + j*16, sk2 + j*8);
            CP16(dk + 2*FARR + j*16, sv + j*8);
            CP16(dk + 3*FARR + j*16, sv2 + j*8);
        }
        CPC();
    }

    float acco[8][4];
    #pragma unroll
    for (int i = 0; i < 8; i++)
        #pragma unroll
        for (int p = 0; p < 4; p++) acco[i][p] = 0.f;
    float m0 = -3.402823466e38f, m1 = -3.402823466e38f, l0s = 0.f, l1s = 0.f;

    for (int t = 0; t < LTOK/128; t++) {
        CPW0();
        __syncthreads();
        if (t + 1 < LTOK/128) {
            unsigned dk = sb + FST((t+1)&1) + (row*FQS + half*32)*2;
            size_t ro = base + (size_t)((t+1)*128+row)*1536 + h*64 + half*32;
            const __nv_bfloat16* sk = qh + ro + 512;
            const __nv_bfloat16* sk2 = ql + ro + 512;
            const __nv_bfloat16* sv = qh + ro + 1024;
            const __nv_bfloat16* sv2 = ql + ro + 1024;
            #pragma unroll
            for (int j = 0; j < 4; j++) {
                CP16(dk + j*16, sk + j*8);
                CP16(dk + FARR + j*16, sk2 + j*8);
                CP16(dk + 2*FARR + j*16, sv + j*8);
                CP16(dk + 3*FARR + j*16, sv2 + j*8);
            }
            CPC();
        }
        unsigned sKH = sb + FST(t&1);
        unsigned sKL = sKH + FARR;
        unsigned sVH = sKH + 2*FARR;
        unsigned sVL = sKH + 3*FARR;

        float accs[16][4];
        #pragma unroll
        for (int nt = 0; nt < 16; nt++)
            #pragma unroll
            for (int p = 0; p < 4; p++) accs[nt][p] = 0.f;
        #pragma unroll
        for (int ks = 0; ks < 4; ks++) {
            int k0 = ks*16;
            unsigned aqh[4], aql[4];
            unsigned aoff = (unsigned)((wid*16 + (q8&1)*8 + lr8)*FQS + k0 + (q8>>1)*8)*2;
            ldmx4(aqh, sb + FQH + aoff);
            ldmx4(aql, sb + FQL + aoff);
            #pragma unroll
            for (int ntp = 0; ntp < 8; ntp++) {
                unsigned boff = (unsigned)((ntp*16 + (q8>>1)*8 + lr8)*FQS + k0 + (q8&1)*8)*2;
                unsigned bh4[4], bl4[4];
                ldmx4(bh4, sKH + boff);
                ldmx4(bl4, sKL + boff);
                mma16816(accs[2*ntp],   aqh, bh4);
                mma16816(accs[2*ntp],   aqh, bl4);
                mma16816(accs[2*ntp],   aql, bh4);
                mma16816(accs[2*ntp+1], aqh, bh4+2);
                mma16816(accs[2*ntp+1], aqh, bl4+2);
                mma16816(accs[2*ntp+1], aql, bh4+2);
            }
        }

        float mx0 = -3.402823466e38f, mx1 = -3.402823466e38f;
        #pragma unroll
        for (int nt = 0; nt < 16; nt++) {
            mx0 = fmaxf(mx0, fmaxf(accs[nt][0], accs[nt][1]));
            mx1 = fmaxf(mx1, fmaxf(accs[nt][2], accs[nt][3]));
        }
        mx0 = fmaxf(mx0, __shfl_xor_sync(0xffffffffu, mx0, 1));
        mx0 = fmaxf(mx0, __shfl_xor_sync(0xffffffffu, mx0, 2));
        mx1 = fmaxf(mx1, __shfl_xor_sync(0xffffffffu, mx1, 1));
        mx1 = fmaxf(mx1, __shfl_xor_sync(0xffffffffu, mx1, 2));
        float mn0 = fmaxf(m0, mx0), mn1 = fmaxf(m1, mx1);
        float c0 = __expf(m0 - mn0), c1 = __expf(m1 - mn1);
        float s0 = 0.f, s1 = 0.f;
        #pragma unroll
        for (int nt = 0; nt < 16; nt++) {
            accs[nt][0] = __expf(accs[nt][0] - mn0);
            accs[nt][1] = __expf(accs[nt][1] - mn0);
            accs[nt][2] = __expf(accs[nt][2] - mn1);
            accs[nt][3] = __expf(accs[nt][3] - mn1);
            s0 += accs[nt][0] + accs[nt][1];
            s1 += accs[nt][2] + accs[nt][3];
        }
        s0 += __shfl_xor_sync(0xffffffffu, s0, 1);
        s0 += __shfl_xor_sync(0xffffffffu, s0, 2);
        s1 += __shfl_xor_sync(0xffffffffu, s1, 1);
        s1 += __shfl_xor_sync(0xffffffffu, s1, 2);
        l0s = l0s * c0 + s0;
        l1s = l1s * c1 + s1;
        m0 = mn0; m1 = mn1;
        #pragma unroll
        for (int i = 0; i < 8; i++) {
            acco[i][0] *= c0; acco[i][1] *= c0;
            acco[i][2] *= c1; acco[i][3] *= c1;
        }

        #pragma unroll
        for (int pks = 0; pks < 8; pks++) {
            unsigned aph[4], apl[4];
            split2(accs[2*pks][0],   accs[2*pks][1],   aph[0], apl[0]);
            split2(accs[2*pks][2],   accs[2*pks][3],   aph[1], apl[1]);
            split2(accs[2*pks+1][0], accs[2*pks+1][1], aph[2], apl[2]);
            split2(accs[2*pks+1][2], accs[2*pks+1][3], aph[3], apl[3]);
            #pragma unroll
            for (int ntp2 = 0; ntp2 < 4; ntp2++) {
                unsigned voff = (unsigned)((pks*16 + (q8&1)*8 + lr8)*FQS + ntp2*16 + (q8>>1)*8)*2;
                unsigned bvh[4], bvl[4];
                ldmx4t(bvh, sVH + voff);
                ldmx4t(bvl, sVL + voff);
                mma16816(acco[2*ntp2],   aph, bvh);
                mma16816(acco[2*ntp2],   aph, bvl);
                mma16816(acco[2*ntp2],   apl, bvh);
                mma16816(acco[2*ntp2+1], aph, bvh+2);
                mma16816(acco[2*ntp2+1], aph, bvl+2);
                mma16816(acco[2*ntp2+1], apl, bvh+2);
            }
        }
    }

    float inv0 = 1.0f / l0s, inv1 = 1.0f / l1s;
    int orow = q0 + wid*16 + g;
    #pragma unroll
    for (int nt2 = 0; nt2 < 8; nt2++) {
        int col = h*64 + nt2*8 + tg*2;
        unsigned hh, ll;
        split2(acco[nt2][0]*inv0, acco[nt2][1]*inv0, hh, ll);
        *(unsigned*)(oh + (size_t)(b*LTOK + orow) * EDIM + col) = hh;
        *(unsigned*)(ol + (size_t)(b*LTOK + orow) * EDIM + col) = ll;
        split2(acco[nt2][2]*inv1, acco[nt2][3]*inv1, hh, ll);
        *(unsigned*)(oh + (size_t)(b*LTOK + orow + 8) * EDIM + col) = hh;
        *(unsigned*)(ol + (size_t)(b*LTOK + orow + 8) * EDIM + col) = ll;
    }
}

// ---------------- FPS -------------------------------------------------------
__global__ __launch_bounds__(512) void fps_kernel(const float* __restrict__ xyzs) {
    int blk = blockIdx.x;
    int b = blk / TO, j = blk % TO;
    const float* P = xyzs + (size_t)(b*NT + 2*j)*NP*3;
    int tid = threadIdx.x;
    float px[8], py[8], pz[8], dist[8];
    #pragma unroll
    for (int i = 0; i < 8; i++) {
        int p = tid + i*512;
        px[i] = P[p*3+0]; py[i] = P[p*3+1]; pz[i] = P[p*3+2];
        dist[i] = 1e10f;
    }
    __shared__ float sbx, sby, sbz;
    __shared__ float swv[16];
    __shared__ int   swi[16];
    float* anch = g_anchor + (size_t)blk*MM*3;
    if (tid == 0) {
        sbx = P[0]; sby = P[1]; sbz = P[2];
        anch[0] = P[0]; anch[1] = P[1]; anch[2] = P[2];
    }
    __syncthreads();
    for (int s = 1; s < MM; s++) {
        float bx = sbx, by = sby, bz = sbz;
        float bestv = -1.0f; int besti = 0x7fffffff;
        #pragma unroll
        for (int i = 0; i < 8; i++) {
            float dx = __fsub_rn(px[i], bx);
            float dy = __fsub_rn(py[i], by);
            float dz = __fsub_rn(pz[i], bz);
            float d = __fadd_rn(__fadd_rn(__fmul_rn(dx,dx), __fmul_rn(dy,dy)), __fmul_rn(dz,dz));
            float nd = fminf(dist[i], d);
            dist[i] = nd;
            int p = tid + i*512;
            if (nd > bestv || (nd == bestv && p < besti)) { bestv = nd; besti = p; }
        }
        #pragma unroll
        for (int off = 16; off; off >>= 1) {
            float ov = __shfl_down_sync(0xffffffffu, bestv, off);
            int   oi = __shfl_down_sync(0xffffffffu, besti, off);
            if (ov > bestv || (ov == bestv && oi < besti)) { bestv = ov; besti = oi; }
        }
        if ((tid & 31) == 0) { swv[tid>>5] = bestv; swi[tid>>5] = besti; }
        __syncthreads();
        if (tid == 0) {
            float v = swv[0]; int ii = swi[0];
            #pragma unroll
            for (int w = 1; w < 16; w++)
                if (swv[w] > v || (swv[w] == v && swi[w] < ii)) { v = swv[w]; ii = swi[w]; }
            float x0 = P[ii*3+0], y0 = P[ii*3+1], z0 = P[ii*3+2];
            sbx = x0; sby = y0; sbz = z0;
            anch[s*3+0] = x0; anch[s*3+1] = y0; anch[s*3+2] = z0;
        }
        __syncthreads();
    }
}

// ---------------- Ball query ------------------------------------------------
__global__ __launch_bounds__(128) void ball_kernel(const float* __restrict__ xyzs) {
    int w = blockIdx.x*4 + (threadIdx.x >> 5);
    int lane = threadIdx.x & 31;
    int o = w / NTOK;
    int tok = w % NTOK;
    int b = tok / LTOK, loc = tok % LTOK, j = loc / MM;
    int pf = 2*j + o;
    int of = (pf == 0) ? 0 : (pf - 1);
    const float* P = xyzs + (size_t)(b*NT + of)*NP*3;
    float ax = g_anchor[tok*3+0], ay = g_anchor[tok*3+1], az = g_anchor[tok*3+2];
    int* out = g_ball + ((size_t)o*NTOK + tok)*KSAMP;
    int cnt = 0, first = 0; bool found = false;
    for (int base = 0; base < NP; base += 32) {
        int p = base + lane;
        float x = P[p*3+0], y = P[p*3+1], z = P[p*3+2];
        float dx = __fsub_rn(ax,x), dy = __fsub_rn(ay,y), dz = __fsub_rn(az,z);
        float d2 = __fadd_rn(__fadd_rn(__fmul_rn(dx,dx), __fmul_rn(dy,dy)), __fmul_rn(dz,dz));
        bool inside = d2 < RAD2;
        unsigned msk = __ballot_sync(0xffffffffu, inside);
        if (!found && msk) { first = base + __ffs(msk) - 1; found = true; }
        int pos = cnt + __popc(msk & ((1u << lane) - 1u));
        if (inside && pos < KSAMP) out[pos] = p;
        cnt += __popc(msk);
        if (cnt >= KSAMP) break;
    }
    if (lane >= cnt) out[lane] = found ? first : 0;
}

// ---------------- grouped conv + max pool (R10 structure, wd3 folded) ------
__global__ __launch_bounds__(128) void conv_kernel(
    const float* __restrict__ xyzs, const float* __restrict__ oldf,
    const float* __restrict__ Wd, const float* __restrict__ Wf,
    float* __restrict__ dout)
{
    int tok = blockIdx.x;
    int b = tok / LTOK, loc = tok % LTOK, j = loc / MM;
    int tid = threadIdx.x;
    __shared__ float sd[KSAMP][4];
    __shared__ float sf[KSAMP][2];
    float ax = g_anchor[tok*3+0], ay = g_anchor[tok*3+1], az = g_anchor[tok*3+2];
    float wd[4][4], wf[4][2], vmax[4];
    #pragma unroll
    for (int r = 0; r < 4; r++) {
        int d = tid + 128*r;
        float4 w4 = *(const float4*)(Wd + d*4);
        wd[r][0] = w4.x; wd[r][1] = w4.y; wd[r][2] = w4.z; wd[r][3] = w4.w;
        float2 w2 = *(const float2*)(Wf + d*2);
        wf[r][0] = w2.x; wf[r][1] = w2.y;
        vmax[r] = -3.402823466e38f;
    }
    for (int o = 0; o < 3; o++) {
        int pf = 2*j + o;
        int of = (pf == 0) ? 0 : (pf - 1);
        const float* P = xyzs + (size_t)(b*NT + of)*NP*3;
        const float* F = oldf + (size_t)(b*NT + of)*2*NP;
        __syncthreads();
        if (tid < KSAMP) {
            int idx = g_ball[((size_t)o*NTOK + tok)*KSAMP + tid];
            sd[tid][0] = P[idx*3+0] - ax;
            sd[tid][1] = P[idx*3+1] - ay;
            sd[tid][2] = P[idx*3+2] - az;
            sf[tid][0] = F[idx];
            sf[tid][1] = F[NP + idx];
        }
        __syncthreads();
        float o3 = (float)(o - 1);
        float cr[4];
        #pragma unroll
        for (int r = 0; r < 4; r++) cr[r] = wd[r][3] * o3;
        #pragma unroll 4
        for (int k = 0; k < KSAMP; k++) {
            float d0 = sd[k][0], d1 = sd[k][1], d2 = sd[k][2];
            float f0 = sf[k][0], f1 = sf[k][1];
            #pragma unroll
            for (int r = 0; r < 4; r++) {
                float de = fmaf(wd[r][0], d0, fmaf(wd[r][1], d1, fmaf(wd[r][2], d2, cr[r])));
                float fe = fmaf(wf[r][1], f1, wf[r][0]*f0);
                vmax[r] = fmaxf(vmax[r], de*fe);
            }
        }
    }
    #pragma unroll
    for (int r = 0; r < 4; r++)
        dout[FEAT_OFF + (size_t)tok*EDIM + tid + 128*r] = vmax[r];
}

// ---------------- pos + contrastive + relu(pos+feat) -----------------------
__global__ __launch_bounds__(512) void embed_kernel(
    const float* __restrict__ pw, const float* __restrict__ pb,
    const float* __restrict__ cw, const float* __restrict__ cb,
    float* __restrict__ dout)
{
    int tok = blockIdx.x;
    int d = threadIdx.x;
    int loc = tok % LTOK, j = loc / MM;
    float ax = g_anchor[tok*3+0], ay = g_anchor[tok*3+1], az = g_anchor[tok*3+2];
    float tv = (float)(j + 1);
    float pos = pw[d*4+0]*ax + pw[d*4+1]*ay + pw[d*4+2]*az + pw[d*4+3]*tv + pb[d];
    float con = cw[d*4+0]*ax + cw[d*4+1]*ay + cw[d*4+2]*az + cw[d*4+3]*tv + cb[d];
    dout[CONTR_OFF + (size_t)tok*EDIM + d] = con;
    float feat = dout[FEAT_OFF + (size_t)tok*EDIM + d];
    g_x[(size_t)tok*EDIM + d] = fmaxf(pos + feat, 0.0f);
}

// ---------------- LayerNorm -> bf16 hi/lo ----------------------------------
__global__ __launch_bounds__(256) void ln_split_kernel(
    const float* __restrict__ x, const float* __restrict__ s,
    const float* __restrict__ bb,
    __nv_bfloat16* __restrict__ outh, __nv_bfloat16* __restrict__ outl)
{
    int tok = blockIdx.x;
    int tid = threadIdx.x;
    const float* row = x + (size_t)tok*EDIM;
    float v0 = row[tid], v1 = row[tid + 256];
    float sum = v0 + v1, sq = v0*v0 + v1*v1;
    #pragma unroll
    for (int off = 16; off; off >>= 1) {
        sum += __shfl_xor_sync(0xffffffffu, sum, off);
        sq  += __shfl_xor_sync(0xffffffffu, sq, off);
    }
    __shared__ float ssum[8], ssq[8];
    if ((tid & 31) == 0) { ssum[tid>>5] = sum; ssq[tid>>5] = sq; }
    __syncthreads();
    float ts = 0.f, tq = 0.f;
    #pragma unroll
    for (int w = 0; w < 8; w++) { ts += ssum[w]; tq += ssq[w]; }
    float mu = ts * (1.0f/512.0f);
    float var = tq * (1.0f/512.0f) - mu*mu;
    float rstd = rsqrtf(var + 1e-5f);
    float y0 = (v0 - mu)*rstd*s[tid] + bb[tid];
    float y1 = (v1 - mu)*rstd*s[tid+256] + bb[tid+256];
    __nv_bfloat16 h0 = __float2bfloat16(y0);
    __nv_bfloat16 h1 = __float2bfloat16(y1);
    outh[(size_t)tok*EDIM + tid]       = h0;
    outh[(size_t)tok*EDIM + tid + 256] = h1;
    outl[(size_t)tok*EDIM + tid]       = __float2bfloat16(y0 - __bfloat162float(h0));
    outl[(size_t)tok*EDIM + tid + 256] = __float2bfloat16(y1 - __bfloat162float(h1));
}

// ---------------- fp32 LayerNorm (head) ------------------------------------
__global__ __launch_bounds__(256) void ln_kernel(
    const float* __restrict__ x, const float* __restrict__ s,
    const float* __restrict__ bb, float* __restrict__ out)
{
    int tok = blockIdx.x;
    int tid = threadIdx.x;
    const float* row = x + (size_t)tok*EDIM;
    float v0 = row[tid], v1 = row[tid + 256];
    float sum = v0 + v1, sq = v0*v0 + v1*v1;
    #pragma unroll
    for (int off = 16; off; off >>= 1) {
        sum += __shfl_xor_sync(0xffffffffu, sum, off);
        sq  += __shfl_xor_sync(0xffffffffu, sq, off);
    }
    __shared__ float ssum[8], ssq[8];
    if ((tid & 31) == 0) { ssum[tid>>5] = sum; ssq[tid>>5] = sq; }
    __syncthreads();
    float ts = 0.f, tq = 0.f;
    #pragma unroll
    for (int w = 0; w < 8; w++) { ts += ssum[w]; tq += ssq[w]; }
    float mu = ts * (1.0f/512.0f);
    float var = tq * (1.0f/512.0f) - mu*mu;
    float rstd = rsqrtf(var + 1e-5f);
    out[(size_t)tok*EDIM + tid]       = (v0 - mu)*rstd*s[tid] + bb[tid];
    out[(size_t)tok*EDIM + tid + 256] = (v1 - mu)*rstd*s[tid+256] + bb[tid+256];
}

// ---------------- head ------------------------------------------------------
__global__ __launch_bounds__(512) void pool1_kernel() {
    int chunk = blockIdx.x, b = blockIdx.y;
    int d = threadIdx.x;
    float v = -3.402823466e38f;
    const float* p = g_x + ((size_t)b*LTOK + chunk*128)*EDIM + d;
    #pragma unroll 4
    for (int i = 0; i < 128; i++) v = fmaxf(v, p[(size_t)i*EDIM]);
    g_poolp[((size_t)b*12 + chunk)*EDIM + d] = v;
}
__global__ __launch_bounds__(512) void pool2_kernel() {
    int b = blockIdx.x;
    int d = threadIdx.x;
    float v = -3.402823466e38f;
    #pragma unroll
    for (int c = 0; c < 12; c++) v = fmaxf(v, g_poolp[((size_t)b*12 + c)*EDIM + d]);
    g_pool[b*EDIM + d] = v;
}
__global__ __launch_bounds__(256) void head1_kernel(
    const float* __restrict__ W, const float* __restrict__ bias)
{
    int out = blockIdx.x*8 + (threadIdx.x >> 5);
    int lane = threadIdx.x & 31;
    int b = out >> 10, jj = out & 1023;
    const float* xr = g_hln + b*EDIM;
    const float* wr = W + (size_t)jj*EDIM;
    float s = 0.f;
    for (int d = lane; d < EDIM; d += 32) s += xr[d]*wr[d];
    #pragma unroll
    for (int off = 16; off; off >>= 1) s += __shfl_xor_sync(0xffffffffu, s, off);
    if (lane == 0) g_h1[out] = gelu_exact(s + bias[jj]);
}
__global__ __launch_bounds__(128) void head2_kernel(
    const float* __restrict__ W, const float* __restrict__ bias,
    float* __restrict__ dout)
{
    int out = blockIdx.x*4 + (threadIdx.x >> 5);
    int lane = threadIdx.x & 31;
    int b = out / NCLS, c = out % NCLS;
    float s = 0.f;
    for (int d = lane; d < MLPD; d += 32) s += g_h1[b*MLPD + d]*W[(size_t)c*MLPD + d];
    #pragma unroll
    for (int off = 16; off; off >>= 1) s += __shfl_xor_sync(0xffffffffu, s, off);
    if (lane == 0) dout[out] = s + bias[c];
}

// ---------------- launch ---------------------------------------------------
extern "C" void kernel_launch(void* const* d_in, const int* in_sizes, int n_in,
                              void* d_out, int out_size) {
    const float* xyzs      = (const float*)d_in[0];
    const float* oldf      = (const float*)d_in[1];
    const float* conv_d_w  = (const float*)d_in[2];
    const float* conv_f_w  = (const float*)d_in[3];
    const float* pos_w     = (const float*)d_in[4];
    const float* pos_b     = (const float*)d_in[5];
    const float* contr_w   = (const float*)d_in[6];
    const float* contr_b   = (const float*)d_in[7];
    const float* ln1_s     = (const float*)d_in[8];
    const float* ln1_b     = (const float*)d_in[9];
    const float* qkv_w     = (const float*)d_in[10];
    const float* out_w     = (const float*)d_in[11];
    const float* out_b     = (const float*)d_in[12];
    const float* ln2_s     = (const float*)d_in[13];
    const float* ln2_b     = (const float*)d_in[14];
    const float* ff1_w     = (const float*)d_in[15];
    const float* ff1_b     = (const float*)d_in[16];
    const float* ff2_w     = (const float*)d_in[17];
    const float* ff2_b     = (const float*)d_in[18];
    const float* head_ln_s = (const float*)d_in[19];
    const float* head_ln_b = (const float*)d_in[20];
    const float* head1_w   = (const float*)d_in[21];
    const float* head1_b   = (const float*)d_in[22];
    const float* head2_w   = (const float*)d_in[23];
    const float* head2_b   = (const float*)d_in[24];
    float* out = (float*)d_out;

    float *px, *ppool, *phln;
    __nv_bfloat16 *pwh, *pwl, *phh, *phl, *pqh, *pql, *poh, *pol, *pf1h, *pf1l;
    cudaGetSymbolAddress((void**)&px,    g_x);
    cudaGetSymbolAddress((void**)&ppool, g_pool);
    cudaGetSymbolAddress((void**)&phln,  g_hln);
    cudaGetSymbolAddress((void**)&pwh,   g_wh);
    cudaGetSymbolAddress((void**)&pwl,   g_wl);
    cudaGetSymbolAddress((void**)&phh,   g_hh);
    cudaGetSymbolAddress((void**)&phl,   g_hl);
    cudaGetSymbolAddress((void**)&pqh,   g_qh);
    cudaGetSymbolAddress((void**)&pql,   g_ql);
    cudaGetSymbolAddress((void**)&poh,   g_oh);
    cudaGetSymbolAddress((void**)&pol,   g_ol);
    cudaGetSymbolAddress((void**)&pf1h,  g_f1h);
    cudaGetSymbolAddress((void**)&pf1l,  g_f1l);

    cudaFuncSetAttribute(flash_kernel, cudaFuncAttributeMaxDynamicSharedMemorySize, FA_SMEM);
    cudaFuncSetAttribute(tgemm_b, cudaFuncAttributeMaxDynamicSharedMemorySize, G_SMEM);
    cudaFuncSetAttribute(tgemm_b64, cudaFuncAttributeMaxDynamicSharedMemorySize, G64_SMEM);

    // ---- one-time weight split (single fused launch; graph-safe) ----
    wsplit_all_kernel<<<WTOT/1024, 256>>>(qkv_w, out_w, ff1_w, ff2_w, pwh, pwl);

    fps_kernel<<<48, 512>>>(xyzs);
    ball_kernel<<<(3*NTOK)/4, 128>>>(xyzs);
    conv_kernel<<<NTOK, 128>>>(xyzs, oldf, conv_d_w, conv_f_w, out);
    embed_kernel<<<NTOK, 512>>>(pos_w, pos_b, contr_w, contr_b, out);

    for (int l = 0; l < 4; l++) {
        ln_split_kernel<<<NTOK, 256>>>(px, ln1_s + l*EDIM, ln1_b + l*EDIM, phh, phl);
        // QKV: split output (Q pre-scaled by 1/8)
        tgemm_b<<<dim3(12,48,1), 256, G_SMEM>>>(
            phh, phl, pwh + WQKV_OFF + (size_t)l*1536*512, pwl + WQKV_OFF + (size_t)l*1536*512,
            nullptr, nullptr, pqh, pql,
            512, 512, 512, 1536, 0,0,0, 1,1);
        // fused attention -> o hi/lo
        flash_kernel<<<dim3(LTOK/128, NB*NHEAD), 256, FA_SMEM>>>(pqh, pql, poh, pol);
        // out proj + residual (fp32 out) — BN=64
        tgemm_b64<<<dim3(8,48,1), 256, G64_SMEM>>>(
            poh, pol, pwh + WOUT_OFF + (size_t)l*512*512, pwl + WOUT_OFF + (size_t)l*512*512,
            out_b + l*EDIM, px, nullptr, nullptr,
            512, 512, 512, 512, 0,1,1, 0);
        ln_split_kernel<<<NTOK, 256>>>(px, ln2_s + l*EDIM, ln2_b + l*EDIM, phh, phl);
        // ff1 + gelu: split output — BN=64
        tgemm_b64<<<dim3(16,48,1), 256, G64_SMEM>>>(
            phh, phl, pwh + WFF1_OFF + (size_t)l*1024*512, pwl + WFF1_OFF + (size_t)l*1024*512,
            ff1_b + l*MLPD, nullptr, pf1h, pf1l,
            512, 512, 512, 1024, 1,0,1, 1);
        // ff2 + residual (fp32 out) — BN=64
        tgemm_b64<<<dim3(8,48,1), 256, G64_SMEM>>>(
            pf1h, pf1l, pwh + WFF2_OFF + (size_t)l*512*1024, pwl + WFF2_OFF + (size_t)l*512*1024,
            ff2_b + l*EDIM, px, nullptr, nullptr,
            1024, 1024, 1024, 512, 0,1,1, 0);
    }

    pool1_kernel<<<dim3(12, NB), 512>>>();
    pool2_kernel<<<NB, 512>>>();
    ln_kernel<<<NB, 256>>>(ppool, head_ln_s, head_ln_b, phln);
    head1_kernel<<<(NB*MLPD)/8, 256>>>(head1_w, head1_b);
    head2_kernel<<<NB*NCLS/4, 128>>>(head2_w, head2_b, out);
}

// round 13
// speedup vs baseline: 1.0927x; 1.0820x over previous
#include <cuda_runtime.h>
#include <cuda_bf16.h>
#include <cstdint>
#include <math.h>

#define NB 4
#define NT 24
#define NP 4096
#define MM 128
#define TO 12
#define LTOK 1536
#define NTOK 6144
#define EDIM 512
#define NHEAD 8
#define DHEAD 64
#define MLPD 1024
#define NCLS 30
#define KSAMP 32
#define RAD2 0.09f

#define CONTR_OFF 120
#define FEAT_OFF (120 + NTOK*EDIM)

// weight-split buffer offsets (elements)
#define WQKV_OFF 0
#define WOUT_OFF 3145728
#define WFF1_OFF 4194304
#define WFF2_OFF 6291456
#define WTOT     8388608

// ---------------- scratch (device globals; no cudaMalloc allowed) ----------
__device__ __align__(256) float g_anchor[NTOK*3];
__device__ __align__(256) int   g_ball[3*NTOK*KSAMP];
__device__ __align__(256) float g_x[NTOK*EDIM];
__device__ __align__(256) float g_pool[NB*EDIM];
__device__ __align__(256) float g_poolp[NB*12*EDIM];
__device__ __align__(256) float g_hln[NB*EDIM];
__device__ __align__(256) float g_h1[NB*MLPD];

__device__ __align__(256) __nv_bfloat16 g_wh[WTOT];
__device__ __align__(256) __nv_bfloat16 g_wl[WTOT];
__device__ __align__(256) __nv_bfloat16 g_hh[NTOK*EDIM];
__device__ __align__(256) __nv_bfloat16 g_hl[NTOK*EDIM];
__device__ __align__(256) __nv_bfloat16 g_qh[NTOK*1536];
__device__ __align__(256) __nv_bfloat16 g_ql[NTOK*1536];
__device__ __align__(256) __nv_bfloat16 g_oh[NTOK*EDIM];
__device__ __align__(256) __nv_bfloat16 g_ol[NTOK*EDIM];
__device__ __align__(256) __nv_bfloat16 g_f1h[NTOK*MLPD];
__device__ __align__(256) __nv_bfloat16 g_f1l[NTOK*MLPD];

__device__ __forceinline__ float gelu_exact(float x){
    return 0.5f*x*(1.0f+erff(x*0.70710678118654752440f));
}

// ==================== PTX helpers ==========================================
__device__ __forceinline__ void mma16816(float* c, const unsigned* a, const unsigned* b){
    asm volatile("mma.sync.aligned.m16n8k16.row.col.f32.bf16.bf16.f32 "
        "{%0,%1,%2,%3}, {%4,%5,%6,%7}, {%8,%9}, {%0,%1,%2,%3};"
        : "+f"(c[0]),"+f"(c[1]),"+f"(c[2]),"+f"(c[3])
        : "r"(a[0]),"r"(a[1]),"r"(a[2]),"r"(a[3]), "r"(b[0]),"r"(b[1]));
}
__device__ __forceinline__ void split2(float x, float y, unsigned& hi, unsigned& lo){
    __nv_bfloat16 hx = __float2bfloat16(x), hy = __float2bfloat16(y);
    float rx = x - __bfloat162float(hx), ry = y - __bfloat162float(hy);
    __nv_bfloat16 lx = __float2bfloat16(rx), ly = __float2bfloat16(ry);
    hi = (unsigned)__bfloat16_as_ushort(hx) | ((unsigned)__bfloat16_as_ushort(hy) << 16);
    lo = (unsigned)__bfloat16_as_ushort(lx) | ((unsigned)__bfloat16_as_ushort(ly) << 16);
}
__device__ __forceinline__ unsigned smem_u32(const void* p){
    unsigned a;
    asm("{ .reg .u64 t; cvta.to.shared.u64 t, %1; cvt.u32.u64 %0, t; }" : "=r"(a) : "l"(p));
    return a;
}
__device__ __forceinline__ void ldmx4(unsigned* r, unsigned addr){
    asm volatile("ldmatrix.sync.aligned.m8n8.x4.shared.b16 {%0,%1,%2,%3}, [%4];"
        : "=r"(r[0]),"=r"(r[1]),"=r"(r[2]),"=r"(r[3]) : "r"(addr));
}
__device__ __forceinline__ void ldmx4t(unsigned* r, unsigned addr){
    asm volatile("ldmatrix.sync.aligned.m8n8.x4.trans.shared.b16 {%0,%1,%2,%3}, [%4];"
        : "=r"(r[0]),"=r"(r[1]),"=r"(r[2]),"=r"(r[3]) : "r"(addr));
}
#define CP16(d, s) asm volatile("cp.async.cg.shared.global [%0], [%1], 16;" :: "r"(d), "l"(s) : "memory")
#define CPC() asm volatile("cp.async.commit_group;" ::: "memory")
#define CPW0() asm volatile("cp.async.wait_group 0;" ::: "memory")

// ---------------- fused weight split prep (single launch) -------------------
__global__ __launch_bounds__(256) void wsplit_all_kernel(
    const float* __restrict__ qkv_w, const float* __restrict__ out_w,
    const float* __restrict__ ff1_w, const float* __restrict__ ff2_w,
    __nv_bfloat16* __restrict__ hi, __nv_bfloat16* __restrict__ lo)
{
    int i = (blockIdx.x*256 + threadIdx.x)*4;
    if (i >= WTOT) return;
    const float* src;
    int off;
    if (i < WOUT_OFF)       { src = qkv_w; off = i - WQKV_OFF; }
    else if (i < WFF1_OFF)  { src = out_w; off = i - WOUT_OFF; }
    else if (i < WFF2_OFF)  { src = ff1_w; off = i - WFF1_OFF; }
    else                    { src = ff2_w; off = i - WFF2_OFF; }
    float4 v = *(const float4*)(src + off);
    unsigned h0, l0, h1, l1;
    split2(v.x, v.y, h0, l0); split2(v.z, v.w, h1, l1);
    *(unsigned*)(hi+i) = h0; *(unsigned*)(hi+i+2) = h1;
    *(unsigned*)(lo+i) = l0; *(unsigned*)(lo+i+2) = l1;
}

#define LDT 40                       // smem row stride in bf16 (32 + 8 pad)
#define GARR (128*LDT*2)             // 10240 B per 128-row array
#define GSTAGE (4*GARR)              // 40960 B per stage
#define G_SMEM (2*GSTAGE)            // 81920 B

// ============ GEMM BN=128, pre-split bf16, cp.async, ldmatrix ==============
__global__ __launch_bounds__(256) void tgemm_b(
    const __nv_bfloat16* __restrict__ AH_, const __nv_bfloat16* __restrict__ AL_,
    const __nv_bfloat16* __restrict__ WH_, const __nv_bfloat16* __restrict__ WL_,
    const float* __restrict__ bias, float* __restrict__ Cf,
    __nv_bfloat16* __restrict__ CH_, __nv_bfloat16* __restrict__ CL_,
    int K, int lda, int ldw, int ldc,
    int act, int resid, int hasb, int split, int qscale)
{
    extern __shared__ char smem[];
    unsigned sb = smem_u32(smem);

    int tid = threadIdx.x, wid = tid >> 5, lane = tid & 31;
    int g = lane >> 2, tg = lane & 3;
    int q8 = lane >> 3, lr8 = lane & 7;
    int rw = (wid >> 2) * 64, cw = (wid & 3) * 32;
    int bm = blockIdx.y * 128, bn = blockIdx.x * 128;

    float acc[4][4][4];
    #pragma unroll
    for (int i = 0; i < 4; i++)
        #pragma unroll
        for (int j = 0; j < 4; j++)
            #pragma unroll
            for (int p = 0; p < 4; p++) acc[i][j][p] = 0.f;

    int row = tid >> 1, half = tid & 1;
    int nch = K >> 5;

    {
        unsigned dst = sb + (row*LDT + half*16)*2;
        const __nv_bfloat16* a = AH_ + (size_t)(bm+row)*lda + half*16;
        const __nv_bfloat16* a2 = AL_ + (size_t)(bm+row)*lda + half*16;
        const __nv_bfloat16* w = WH_ + (size_t)(bn+row)*ldw + half*16;
        const __nv_bfloat16* w2 = WL_ + (size_t)(bn+row)*ldw + half*16;
        CP16(dst, a); CP16(dst+16, a+8);
        CP16(dst+GARR, a2); CP16(dst+GARR+16, a2+8);
        CP16(dst+2*GARR, w); CP16(dst+2*GARR+16, w+8);
        CP16(dst+3*GARR, w2); CP16(dst+3*GARR+16, w2+8);
        CPC();
    }

    for (int c = 0; c < nch; c++) {
        CPW0();
        __syncthreads();
        if (c + 1 < nch) {
            unsigned dst = sb + ((c+1)&1)*GSTAGE + (row*LDT + half*16)*2;
            const __nv_bfloat16* a = AH_ + (size_t)(bm+row)*lda + (c+1)*32 + half*16;
            const __nv_bfloat16* a2 = AL_ + (size_t)(bm+row)*lda + (c+1)*32 + half*16;
            const __nv_bfloat16* w = WH_ + (size_t)(bn+row)*ldw + (c+1)*32 + half*16;
            const __nv_bfloat16* w2 = WL_ + (size_t)(bn+row)*ldw + (c+1)*32 + half*16;
            CP16(dst, a); CP16(dst+16, a+8);
            CP16(dst+GARR, a2); CP16(dst+GARR+16, a2+8);
            CP16(dst+2*GARR, w); CP16(dst+2*GARR+16, w+8);
            CP16(dst+3*GARR, w2); CP16(dst+3*GARR+16, w2+8);
            CPC();
        }
        unsigned sAH = sb + (c&1)*GSTAGE;
        unsigned sAL = sAH + GARR;
        unsigned sWH = sAH + 2*GARR;
        unsigned sWL = sAH + 3*GARR;
        #pragma unroll
        for (int ks = 0; ks < 2; ks++) {
            int k0 = ks * 16;
            unsigned ah[4][4], al[4][4], bh[2][4], bl[2][4];
            #pragma unroll
            for (int mt = 0; mt < 4; mt++) {
                unsigned off = (unsigned)((rw + mt*16 + (q8&1)*8 + lr8)*LDT + k0 + (q8>>1)*8)*2;
                ldmx4(ah[mt], sAH + off);
                ldmx4(al[mt], sAL + off);
            }
            #pragma unroll
            for (int ntp = 0; ntp < 2; ntp++) {
                unsigned off = (unsigned)((cw + ntp*16 + (q8>>1)*8 + lr8)*LDT + k0 + (q8&1)*8)*2;
                ldmx4(bh[ntp], sWH + off);
                ldmx4(bl[ntp], sWL + off);
            }
            #pragma unroll
            for (int mt = 0; mt < 4; mt++)
                #pragma unroll
                for (int nt = 0; nt < 4; nt++) {
                    const unsigned* ph = &bh[nt>>1][(nt&1)*2];
                    const unsigned* pl = &bl[nt>>1][(nt&1)*2];
                    mma16816(acc[mt][nt], ah[mt], ph);
                    mma16816(acc[mt][nt], ah[mt], pl);
                    mma16816(acc[mt][nt], al[mt], ph);
                }
        }
    }
    #pragma unroll
    for (int mt = 0; mt < 4; mt++) {
        #pragma unroll
        for (int nt = 0; nt < 4; nt++) {
            int r0 = bm + rw + mt*16 + g;
            int col = bn + cw + nt*8 + tg*2;
            #pragma unroll
            for (int half2 = 0; half2 < 2; half2++) {
                int r = r0 + half2*8;
                float v0 = acc[mt][nt][half2*2+0];
                float v1 = acc[mt][nt][half2*2+1];
                if (hasb) { v0 += bias[col]; v1 += bias[col+1]; }
                if (act)  { v0 = gelu_exact(v0); v1 = gelu_exact(v1); }
                if (split) {
                    if (qscale && col < 512) { v0 *= 0.125f; v1 *= 0.125f; }
                    unsigned hh, ll;
                    split2(v0, v1, hh, ll);
                    *(unsigned*)(CH_ + (size_t)r*ldc + col) = hh;
                    *(unsigned*)(CL_ + (size_t)r*ldc + col) = ll;
                } else {
                    float* cp = Cf + (size_t)r * ldc + col;
                    if (resid) {
                        float2 old = *(float2*)cp;
                        v0 += old.x; v1 += old.y;
                    }
                    float2 ov = {v0, v1};
                    *(float2*)cp = ov;
                }
            }
        }
    }
}

// ============ GEMM BN=64 (wave fill for narrow N) ==========================
#define G64_WARR (64*LDT*2)              // 5120 B
#define G64_STAGE (2*GARR + 2*G64_WARR)  // 30720 B
#define G64_SMEM (2*G64_STAGE)           // 61440 B

__global__ __launch_bounds__(256) void tgemm_b64(
    const __nv_bfloat16* __restrict__ AH_, const __nv_bfloat16* __restrict__ AL_,
    const __nv_bfloat16* __restrict__ WH_, const __nv_bfloat16* __restrict__ WL_,
    const float* __restrict__ bias, float* __restrict__ Cf,
    __nv_bfloat16* __restrict__ CH_, __nv_bfloat16* __restrict__ CL_,
    int K, int lda, int ldw, int ldc,
    int act, int resid, int hasb, int split)
{
    extern __shared__ char smem[];
    unsigned sb = smem_u32(smem);

    int tid = threadIdx.x, wid = tid >> 5, lane = tid & 31;
    int g = lane >> 2, tg = lane & 3;
    int q8 = lane >> 3, lr8 = lane & 7;
    int rw = (wid >> 2) * 64, cw = (wid & 3) * 16;
    int bm = blockIdx.y * 128, bn = blockIdx.x * 64;

    float acc[4][2][4];
    #pragma unroll
    for (int i = 0; i < 4; i++)
        #pragma unroll
        for (int j = 0; j < 2; j++)
            #pragma unroll
            for (int p = 0; p < 4; p++) acc[i][j][p] = 0.f;

    int row = tid >> 1, half = tid & 1;
    int roww = tid >> 2, colq = (tid & 3) * 8;
    int nch = K >> 5;

    {
        unsigned dstA = sb + (row*LDT + half*16)*2;
        const __nv_bfloat16* a = AH_ + (size_t)(bm+row)*lda + half*16;
        const __nv_bfloat16* a2 = AL_ + (size_t)(bm+row)*lda + half*16;
        CP16(dstA, a); CP16(dstA+16, a+8);
        CP16(dstA+GARR, a2); CP16(dstA+GARR+16, a2+8);
        unsigned dstW = sb + 2*GARR + (roww*LDT + colq)*2;
        const __nv_bfloat16* w = WH_ + (size_t)(bn+roww)*ldw + colq;
        const __nv_bfloat16* w2 = WL_ + (size_t)(bn+roww)*ldw + colq;
        CP16(dstW, w);
        CP16(dstW+G64_WARR, w2);
        CPC();
    }

    for (int c = 0; c < nch; c++) {
        CPW0();
        __syncthreads();
        if (c + 1 < nch) {
            unsigned st = ((c+1)&1)*G64_STAGE;
            unsigned dstA = sb + st + (row*LDT + half*16)*2;
            const __nv_bfloat16* a = AH_ + (size_t)(bm+row)*lda + (c+1)*32 + half*16;
            const __nv_bfloat16* a2 = AL_ + (size_t)(bm+row)*lda + (c+1)*32 + half*16;
            CP16(dstA, a); CP16(dstA+16, a+8);
            CP16(dstA+GARR, a2); CP16(dstA+GARR+16, a2+8);
            unsigned dstW = sb + st + 2*GARR + (roww*LDT + colq)*2;
            const __nv_bfloat16* w = WH_ + (size_t)(bn+roww)*ldw + (c+1)*32 + colq;
            const __nv_bfloat16* w2 = WL_ + (size_t)(bn+roww)*ldw + (c+1)*32 + colq;
            CP16(dstW, w);
            CP16(dstW+G64_WARR, w2);
            CPC();
        }
        unsigned sAH = sb + (c&1)*G64_STAGE;
        unsigned sAL = sAH + GARR;
        unsigned sWH = sAH + 2*GARR;
        unsigned sWL = sWH + G64_WARR;
        #pragma unroll
        for (int ks = 0; ks < 2; ks++) {
            int k0 = ks * 16;
            unsigned ah[4][4], al[4][4], bh4[4], bl4[4];
            #pragma unroll
            for (int mt = 0; mt < 4; mt++) {
                unsigned off = (unsigned)((rw + mt*16 + (q8&1)*8 + lr8)*LDT + k0 + (q8>>1)*8)*2;
                ldmx4(ah[mt], sAH + off);
                ldmx4(al[mt], sAL + off);
            }
            {
                unsigned off = (unsigned)((cw + (q8>>1)*8 + lr8)*LDT + k0 + (q8&1)*8)*2;
                ldmx4(bh4, sWH + off);
                ldmx4(bl4, sWL + off);
            }
            #pragma unroll
            for (int mt = 0; mt < 4; mt++)
                #pragma unroll
                for (int nt = 0; nt < 2; nt++) {
                    mma16816(acc[mt][nt], ah[mt], bh4 + nt*2);
                    mma16816(acc[mt][nt], ah[mt], bl4 + nt*2);
                    mma16816(acc[mt][nt], al[mt], bh4 + nt*2);
                }
        }
    }
    #pragma unroll
    for (int mt = 0; mt < 4; mt++) {
        #pragma unroll
        for (int nt = 0; nt < 2; nt++) {
            int r0 = bm + rw + mt*16 + g;
            int col = bn + cw + nt*8 + tg*2;
            #pragma unroll
            for (int half2 = 0; half2 < 2; half2++) {
                int r = r0 + half2*8;
                float v0 = acc[mt][nt][half2*2+0];
                float v1 = acc[mt][nt][half2*2+1];
                if (hasb) { v0 += bias[col]; v1 += bias[col+1]; }
                if (act)  { v0 = gelu_exact(v0); v1 = gelu_exact(v1); }
                if (split) {
                    unsigned hh, ll;
                    split2(v0, v1, hh, ll);
                    *(unsigned*)(CH_ + (size_t)r*ldc + col) = hh;
                    *(unsigned*)(CL_ + (size_t)r*ldc + col) = ll;
                } else {
                    float* cp = Cf + (size_t)r * ldc + col;
                    if (resid) {
                        float2 old = *(float2*)cp;
                        v0 += old.x; v1 += old.y;
                    }
                    float2 ov = {v0, v1};
                    *(float2*)cp = ov;
                }
            }
        }
    }
}

// ==================== flash attention (KV tile 64, 2 CTAs/SM) ==============
#define FQS 72
#define FQARR (128*FQS*2)            // 18432 B (Q: 128 rows)
#define KARR (64*FQS*2)              // 9216 B (K/V: 64 rows)
#define FST(s) (2*FQARR + (s)*4*KARR)
#define FA_SMEM (2*FQARR + 2*4*KARR) // 110592 B -> 2 CTAs/SM

__global__ __launch_bounds__(256, 2) void flash_kernel(
    const __nv_bfloat16* __restrict__ qh, const __nv_bfloat16* __restrict__ ql,
    __nv_bfloat16* __restrict__ oh, __nv_bfloat16* __restrict__ ol)
{
    extern __shared__ char fsm[];
    unsigned sb = smem_u32(fsm);

    int tid = threadIdx.x, wid = tid >> 5, lane = tid & 31;
    int g = lane >> 2, tg = lane & 3;
    int q8 = lane >> 3, lr8 = lane & 7;
    int z = blockIdx.y;
    int b = z >> 3, h = z & 7;
    size_t base = (size_t)b * LTOK * 1536;
    int q0 = blockIdx.x * 128;

    int row = tid >> 1, half = tid & 1;       // Q load map (128 rows)
    int row64 = tid >> 2, cq = (tid & 3) * 16; // K/V load map (64 rows)

    {
        unsigned dq = sb + (row*FQS + half*32)*2;
        const __nv_bfloat16* sq = qh + base + (size_t)(q0+row)*1536 + h*64 + half*32;
        const __nv_bfloat16* sq2 = ql + base + (size_t)(q0+row)*1536 + h*64 + half*32;
        #pragma unroll
        for (int j = 0; j < 4; j++) {
            CP16(dq + j*16, sq + j*8);
            CP16(dq + FQARR + j*16, sq2 + j*8);
        }
        unsigned dk = sb + FST(0) + (row64*FQS + cq)*2;
        size_t ro = base + (size_t)row64*1536 + h*64 + cq;
        const __nv_bfloat16* sk = qh + ro + 512;
        const __nv_bfloat16* sk2 = ql + ro + 512;
        const __nv_bfloat16* sv = qh + ro + 1024;
        const __nv_bfloat16* sv2 = ql + ro + 1024;
        CP16(dk, sk);                   CP16(dk+16, sk+8);
        CP16(dk+KARR, sk2);             CP16(dk+KARR+16, sk2+8);
        CP16(dk+2*KARR, sv);            CP16(dk+2*KARR+16, sv+8);
        CP16(dk+3*KARR, sv2);           CP16(dk+3*KARR+16, sv2+8);
        CPC();
    }

    float acco[8][4];
    #pragma unroll
    for (int i = 0; i < 8; i++)
        #pragma unroll
        for (int p = 0; p < 4; p++) acco[i][p] = 0.f;
    float m0 = -3.402823466e38f, m1 = -3.402823466e38f, l0s = 0.f, l1s = 0.f;

    for (int t = 0; t < LTOK/64; t++) {
        CPW0();
        __syncthreads();
        if (t + 1 < LTOK/64) {
            unsigned dk = sb + FST((t+1)&1) + (row64*FQS + cq)*2;
            size_t ro = base + (size_t)((t+1)*64+row64)*1536 + h*64 + cq;
            const __nv_bfloat16* sk = qh + ro + 512;
            const __nv_bfloat16* sk2 = ql + ro + 512;
            const __nv_bfloat16* sv = qh + ro + 1024;
            const __nv_bfloat16* sv2 = ql + ro + 1024;
            CP16(dk, sk);                   CP16(dk+16, sk+8);
            CP16(dk+KARR, sk2);             CP16(dk+KARR+16, sk2+8);
            CP16(dk+2*KARR, sv);            CP16(dk+2*KARR+16, sv+8);
            CP16(dk+3*KARR, sv2);           CP16(dk+3*KARR+16, sv2+8);
            CPC();
        }
        unsigned sKH = sb + FST(t&1);
        unsigned sKL = sKH + KARR;
        unsigned sVH = sKH + 2*KARR;
        unsigned sVL = sKH + 3*KARR;

        // ---- S = Q @ K^T (64 kv cols) ----
        float accs[8][4];
        #pragma unroll
        for (int nt = 0; nt < 8; nt++)
            #pragma unroll
            for (int p = 0; p < 4; p++) accs[nt][p] = 0.f;
        #pragma unroll
        for (int ks = 0; ks < 4; ks++) {
            int k0 = ks*16;
            unsigned aqh[4], aql[4];
            unsigned aoff = (unsigned)((wid*16 + (q8&1)*8 + lr8)*FQS + k0 + (q8>>1)*8)*2;
            ldmx4(aqh, sb + aoff);
            ldmx4(aql, sb + FQARR + aoff);
            #pragma unroll
            for (int ntp = 0; ntp < 4; ntp++) {
                unsigned boff = (unsigned)((ntp*16 + (q8>>1)*8 + lr8)*FQS + k0 + (q8&1)*8)*2;
                unsigned bh4[4], bl4[4];
                ldmx4(bh4, sKH + boff);
                ldmx4(bl4, sKL + boff);
                mma16816(accs[2*ntp],   aqh, bh4);
                mma16816(accs[2*ntp],   aqh, bl4);
                mma16816(accs[2*ntp],   aql, bh4);
                mma16816(accs[2*ntp+1], aqh, bh4+2);
                mma16816(accs[2*ntp+1], aqh, bl4+2);
                mma16816(accs[2*ntp+1], aql, bh4+2);
            }
        }

        // ---- online softmax ----
        float mx0 = -3.402823466e38f, mx1 = -3.402823466e38f;
        #pragma unroll
        for (int nt = 0; nt < 8; nt++) {
            mx0 = fmaxf(mx0, fmaxf(accs[nt][0], accs[nt][1]));
            mx1 = fmaxf(mx1, fmaxf(accs[nt][2], accs[nt][3]));
        }
        mx0 = fmaxf(mx0, __shfl_xor_sync(0xffffffffu, mx0, 1));
        mx0 = fmaxf(mx0, __shfl_xor_sync(0xffffffffu, mx0, 2));
        mx1 = fmaxf(mx1, __shfl_xor_sync(0xffffffffu, mx1, 1));
        mx1 = fmaxf(mx1, __shfl_xor_sync(0xffffffffu, mx1, 2));
        float mn0 = fmaxf(m0, mx0), mn1 = fmaxf(m1, mx1);
        float c0 = __expf(m0 - mn0), c1 = __expf(m1 - mn1);
        float s0 = 0.f, s1 = 0.f;
        #pragma unroll
        for (int nt = 0; nt < 8; nt++) {
            accs[nt][0] = __expf(accs[nt][0] - mn0);
            accs[nt][1] = __expf(accs[nt][1] - mn0);
            accs[nt][2] = __expf(accs[nt][2] - mn1);
            accs[nt][3] = __expf(accs[nt][3] - mn1);
            s0 += accs[nt][0] + accs[nt][1];
            s1 += accs[nt][2] + accs[nt][3];
        }
        s0 += __shfl_xor_sync(0xffffffffu, s0, 1);
        s0 += __shfl_xor_sync(0xffffffffu, s0, 2);
        s1 += __shfl_xor_sync(0xffffffffu, s1, 1);
        s1 += __shfl_xor_sync(0xffffffffu, s1, 2);
        l0s = l0s * c0 + s0;
        l1s = l1s * c1 + s1;
        m0 = mn0; m1 = mn1;
        #pragma unroll
        for (int i = 0; i < 8; i++) {
            acco[i][0] *= c0; acco[i][1] *= c0;
            acco[i][2] *= c1; acco[i][3] *= c1;
        }

        // ---- O += P @ V ----
        #pragma unroll
        for (int pks = 0; pks < 4; pks++) {
            unsigned aph[4], apl[4];
            split2(accs[2*pks][0],   accs[2*pks][1],   aph[0], apl[0]);
            split2(accs[2*pks][2],   accs[2*pks][3],   aph[1], apl[1]);
            split2(accs[2*pks+1][0], accs[2*pks+1][1], aph[2], apl[2]);
            split2(accs[2*pks+1][2], accs[2*pks+1][3], aph[3], apl[3]);
            #pragma unroll
            for (int ntp2 = 0; ntp2 < 4; ntp2++) {
                unsigned voff = (unsigned)((pks*16 + (q8&1)*8 + lr8)*FQS + ntp2*16 + (q8>>1)*8)*2;
                unsigned bvh[4], bvl[4];
                ldmx4t(bvh, sVH + voff);
                ldmx4t(bvl, sVL + voff);
                mma16816(acco[2*ntp2],   aph, bvh);
                mma16816(acco[2*ntp2],   aph, bvl);
                mma16816(acco[2*ntp2],   apl, bvh);
                mma16816(acco[2*ntp2+1], aph, bvh+2);
                mma16816(acco[2*ntp2+1], aph, bvl+2);
                mma16816(acco[2*ntp2+1], apl, bvh+2);
            }
        }
    }

    float inv0 = 1.0f / l0s, inv1 = 1.0f / l1s;
    int orow = q0 + wid*16 + g;
    #pragma unroll
    for (int nt2 = 0; nt2 < 8; nt2++) {
        int col = h*64 + nt2*8 + tg*2;
        unsigned hh, ll;
        split2(acco[nt2][0]*inv0, acco[nt2][1]*inv0, hh, ll);
        *(unsigned*)(oh + (size_t)(b*LTOK + orow) * EDIM + col) = hh;
        *(unsigned*)(ol + (size_t)(b*LTOK + orow) * EDIM + col) = ll;
        split2(acco[nt2][2]*inv1, acco[nt2][3]*inv1, hh, ll);
        *(unsigned*)(oh + (size_t)(b*LTOK + orow + 8) * EDIM + col) = hh;
        *(unsigned*)(ol + (size_t)(b*LTOK + orow + 8) * EDIM + col) = ll;
    }
}

// ---------------- FPS -------------------------------------------------------
__global__ __launch_bounds__(512) void fps_kernel(const float* __restrict__ xyzs) {
    int blk = blockIdx.x;
    int b = blk / TO, j = blk % TO;
    const float* P = xyzs + (size_t)(b*NT + 2*j)*NP*3;
    int tid = threadIdx.x;
    float px[8], py[8], pz[8], dist[8];
    #pragma unroll
    for (int i = 0; i < 8; i++) {
        int p = tid + i*512;
        px[i] = P[p*3+0]; py[i] = P[p*3+1]; pz[i] = P[p*3+2];
        dist[i] = 1e10f;
    }
    __shared__ float sbx, sby, sbz;
    __shared__ float swv[16];
    __shared__ int   swi[16];
    float* anch = g_anchor + (size_t)blk*MM*3;
    if (tid == 0) {
        sbx = P[0]; sby = P[1]; sbz = P[2];
        anch[0] = P[0]; anch[1] = P[1]; anch[2] = P[2];
    }
    __syncthreads();
    for (int s = 1; s < MM; s++) {
        float bx = sbx, by = sby, bz = sbz;
        float bestv = -1.0f; int besti = 0x7fffffff;
        #pragma unroll
        for (int i = 0; i < 8; i++) {
            float dx = __fsub_rn(px[i], bx);
            float dy = __fsub_rn(py[i], by);
            float dz = __fsub_rn(pz[i], bz);
            float d = __fadd_rn(__fadd_rn(__fmul_rn(dx,dx), __fmul_rn(dy,dy)), __fmul_rn(dz,dz));
            float nd = fminf(dist[i], d);
            dist[i] = nd;
            int p = tid + i*512;
            if (nd > bestv || (nd == bestv && p < besti)) { bestv = nd; besti = p; }
        }
        #pragma unroll
        for (int off = 16; off; off >>= 1) {
            float ov = __shfl_down_sync(0xffffffffu, bestv, off);
            int   oi = __shfl_down_sync(0xffffffffu, besti, off);
            if (ov > bestv || (ov == bestv && oi < besti)) { bestv = ov; besti = oi; }
        }
        if ((tid & 31) == 0) { swv[tid>>5] = bestv; swi[tid>>5] = besti; }
        __syncthreads();
        if (tid == 0) {
            float v = swv[0]; int ii = swi[0];
            #pragma unroll
            for (int w = 1; w < 16; w++)
                if (swv[w] > v || (swv[w] == v && swi[w] < ii)) { v = swv[w]; ii = swi[w]; }
            float x0 = P[ii*3+0], y0 = P[ii*3+1], z0 = P[ii*3+2];
            sbx = x0; sby = y0; sbz = z0;
            anch[s*3+0] = x0; anch[s*3+1] = y0; anch[s*3+2] = z0;
        }
        __syncthreads();
    }
}

// ---------------- Ball query ------------------------------------------------
__global__ __launch_bounds__(128) void ball_kernel(const float* __restrict__ xyzs) {
    int w = blockIdx.x*4 + (threadIdx.x >> 5);
    int lane = threadIdx.x & 31;
    int o = w / NTOK;
    int tok = w % NTOK;
    int b = tok / LTOK, loc = tok % LTOK, j = loc / MM;
    int pf = 2*j + o;
    int of = (pf == 0) ? 0 : (pf - 1);
    const float* P = xyzs + (size_t)(b*NT + of)*NP*3;
    float ax = g_anchor[tok*3+0], ay = g_anchor[tok*3+1], az = g_anchor[tok*3+2];
    int* out = g_ball + ((size_t)o*NTOK + tok)*KSAMP;
    int cnt = 0, first = 0; bool found = false;
    for (int base = 0; base < NP; base += 32) {
        int p = base + lane;
        float x = P[p*3+0], y = P[p*3+1], z = P[p*3+2];
        float dx = __fsub_rn(ax,x), dy = __fsub_rn(ay,y), dz = __fsub_rn(az,z);
        float d2 = __fadd_rn(__fadd_rn(__fmul_rn(dx,dx), __fmul_rn(dy,dy)), __fmul_rn(dz,dz));
        bool inside = d2 < RAD2;
        unsigned msk = __ballot_sync(0xffffffffu, inside);
        if (!found && msk) { first = base + __ffs(msk) - 1; found = true; }
        int pos = cnt + __popc(msk & ((1u << lane) - 1u));
        if (inside && pos < KSAMP) out[pos] = p;
        cnt += __popc(msk);
        if (cnt >= KSAMP) break;
    }
    if (lane >= cnt) out[lane] = found ? first : 0;
}

// ---------------- grouped conv + max pool (wd3 folded) ---------------------
__global__ __launch_bounds__(128) void conv_kernel(
    const float* __restrict__ xyzs, const float* __restrict__ oldf,
    const float* __restrict__ Wd, const float* __restrict__ Wf,
    float* __restrict__ dout)
{
    int tok = blockIdx.x;
    int b = tok / LTOK, loc = tok % LTOK, j = loc / MM;
    int tid = threadIdx.x;
    __shared__ float sd[KSAMP][4];
    __shared__ float sf[KSAMP][2];
    float ax = g_anchor[tok*3+0], ay = g_anchor[tok*3+1], az = g_anchor[tok*3+2];
    float wd[4][4], wf[4][2], vmax[4];
    #pragma unroll
    for (int r = 0; r < 4; r++) {
        int d = tid + 128*r;
        float4 w4 = *(const float4*)(Wd + d*4);
        wd[r][0] = w4.x; wd[r][1] = w4.y; wd[r][2] = w4.z; wd[r][3] = w4.w;
        float2 w2 = *(const float2*)(Wf + d*2);
        wf[r][0] = w2.x; wf[r][1] = w2.y;
        vmax[r] = -3.402823466e38f;
    }
    for (int o = 0; o < 3; o++) {
        int pf = 2*j + o;
        int of = (pf == 0) ? 0 : (pf - 1);
        const float* P = xyzs + (size_t)(b*NT + of)*NP*3;
        const float* F = oldf + (size_t)(b*NT + of)*2*NP;
        __syncthreads();
        if (tid < KSAMP) {
            int idx = g_ball[((size_t)o*NTOK + tok)*KSAMP + tid];
            sd[tid][0] = P[idx*3+0] - ax;
            sd[tid][1] = P[idx*3+1] - ay;
            sd[tid][2] = P[idx*3+2] - az;
            sf[tid][0] = F[idx];
            sf[tid][1] = F[NP + idx];
        }
        __syncthreads();
        float o3 = (float)(o - 1);
        float cr[4];
        #pragma unroll
        for (int r = 0; r < 4; r++) cr[r] = wd[r][3] * o3;
        #pragma unroll 4
        for (int k = 0; k < KSAMP; k++) {
            float d0 = sd[k][0], d1 = sd[k][1], d2 = sd[k][2];
            float f0 = sf[k][0], f1 = sf[k][1];
            #pragma unroll
            for (int r = 0; r < 4; r++) {
                float de = fmaf(wd[r][0], d0, fmaf(wd[r][1], d1, fmaf(wd[r][2], d2, cr[r])));
                float fe = fmaf(wf[r][1], f1, wf[r][0]*f0);
                vmax[r] = fmaxf(vmax[r], de*fe);
            }
        }
    }
    #pragma unroll
    for (int r = 0; r < 4; r++)
        dout[FEAT_OFF + (size_t)tok*EDIM + tid + 128*r] = vmax[r];
}

// ---------------- pos + contrastive + relu(pos+feat) -----------------------
__global__ __launch_bounds__(512) void embed_kernel(
    const float* __restrict__ pw, const float* __restrict__ pb,
    const float* __restrict__ cw, const float* __restrict__ cb,
    float* __restrict__ dout)
{
    int tok = blockIdx.x;
    int d = threadIdx.x;
    int loc = tok % LTOK, j = loc / MM;
    float ax = g_anchor[tok*3+0], ay = g_anchor[tok*3+1], az = g_anchor[tok*3+2];
    float tv = (float)(j + 1);
    float pos = pw[d*4+0]*ax + pw[d*4+1]*ay + pw[d*4+2]*az + pw[d*4+3]*tv + pb[d];
    float con = cw[d*4+0]*ax + cw[d*4+1]*ay + cw[d*4+2]*az + cw[d*4+3]*tv + cb[d];
    dout[CONTR_OFF + (size_t)tok*EDIM + d] = con;
    float feat = dout[FEAT_OFF + (size_t)tok*EDIM + d];
    g_x[(size_t)tok*EDIM + d] = fmaxf(pos + feat, 0.0f);
}

// ---------------- LayerNorm -> bf16 hi/lo ----------------------------------
__global__ __launch_bounds__(256) void ln_split_kernel(
    const float* __restrict__ x, const float* __restrict__ s,
    const float* __restrict__ bb,
    __nv_bfloat16* __restrict__ outh, __nv_bfloat16* __restrict__ outl)
{
    int tok = blockIdx.x;
    int tid = threadIdx.x;
    const float* row = x + (size_t)tok*EDIM;
    float v0 = row[tid], v1 = row[tid + 256];
    float sum = v0 + v1, sq = v0*v0 + v1*v1;
    #pragma unroll
    for (int off = 16; off; off >>= 1) {
        sum += __shfl_xor_sync(0xffffffffu, sum, off);
        sq  += __shfl_xor_sync(0xffffffffu, sq, off);
    }
    __shared__ float ssum[8], ssq[8];
    if ((tid & 31) == 0) { ssum[tid>>5] = sum; ssq[tid>>5] = sq; }
    __syncthreads();
    float ts = 0.f, tq = 0.f;
    #pragma unroll
    for (int w = 0; w < 8; w++) { ts += ssum[w]; tq += ssq[w]; }
    float mu = ts * (1.0f/512.0f);
    float var = tq * (1.0f/512.0f) - mu*mu;
    float rstd = rsqrtf(var + 1e-5f);
    float y0 = (v0 - mu)*rstd*s[tid] + bb[tid];
    float y1 = (v1 - mu)*rstd*s[tid+256] + bb[tid+256];
    __nv_bfloat16 h0 = __float2bfloat16(y0);
    __nv_bfloat16 h1 = __float2bfloat16(y1);
    outh[(size_t)tok*EDIM + tid]       = h0;
    outh[(size_t)tok*EDIM + tid + 256] = h1;
    outl[(size_t)tok*EDIM + tid]       = __float2bfloat16(y0 - __bfloat162float(h0));
    outl[(size_t)tok*EDIM + tid + 256] = __float2bfloat16(y1 - __bfloat162float(h1));
}

// ---------------- fp32 LayerNorm (head) ------------------------------------
__global__ __launch_bounds__(256) void ln_kernel(
    const float* __restrict__ x, const float* __restrict__ s,
    const float* __restrict__ bb, float* __restrict__ out)
{
    int tok = blockIdx.x;
    int tid = threadIdx.x;
    const float* row = x + (size_t)tok*EDIM;
    float v0 = row[tid], v1 = row[tid + 256];
    float sum = v0 + v1, sq = v0*v0 + v1*v1;
    #pragma unroll
    for (int off = 16; off; off >>= 1) {
        sum += __shfl_xor_sync(0xffffffffu, sum, off);
        sq  += __shfl_xor_sync(0xffffffffu, sq, off);
    }
    __shared__ float ssum[8], ssq[8];
    if ((tid & 31) == 0) { ssum[tid>>5] = sum; ssq[tid>>5] = sq; }
    __syncthreads();
    float ts = 0.f, tq = 0.f;
    #pragma unroll
    for (int w = 0; w < 8; w++) { ts += ssum[w]; tq += ssq[w]; }
    float mu = ts * (1.0f/512.0f);
    float var = tq * (1.0f/512.0f) - mu*mu;
    float rstd = rsqrtf(var + 1e-5f);
    out[(size_t)tok*EDIM + tid]       = (v0 - mu)*rstd*s[tid] + bb[tid];
    out[(size_t)tok*EDIM + tid + 256] = (v1 - mu)*rstd*s[tid+256] + bb[tid+256];
}

// ---------------- head ------------------------------------------------------
__global__ __launch_bounds__(512) void pool1_kernel() {
    int chunk = blockIdx.x, b = blockIdx.y;
    int d = threadIdx.x;
    float v = -3.402823466e38f;
    const float* p = g_x + ((size_t)b*LTOK + chunk*128)*EDIM + d;
    #pragma unroll 4
    for (int i = 0; i < 128; i++) v = fmaxf(v, p[(size_t)i*EDIM]);
    g_poolp[((size_t)b*12 + chunk)*EDIM + d] = v;
}
__global__ __launch_bounds__(512) void pool2_kernel() {
    int b = blockIdx.x;
    int d = threadIdx.x;
    float v = -3.402823466e38f;
    #pragma unroll
    for (int c = 0; c < 12; c++) v = fmaxf(v, g_poolp[((size_t)b*12 + c)*EDIM + d]);
    g_pool[b*EDIM + d] = v;
}
__global__ __launch_bounds__(256) void head1_kernel(
    const float* __restrict__ W, const float* __restrict__ bias)
{
    int out = blockIdx.x*8 + (threadIdx.x >> 5);
    int lane = threadIdx.x & 31;
    int b = out >> 10, jj = out & 1023;
    const float* xr = g_hln + b*EDIM;
    const float* wr = W + (size_t)jj*EDIM;
    float s = 0.f;
    for (int d = lane; d < EDIM; d += 32) s += xr[d]*wr[d];
    #pragma unroll
    for (int off = 16; off; off >>= 1) s += __shfl_xor_sync(0xffffffffu, s, off);
    if (lane == 0) g_h1[out] = gelu_exact(s + bias[jj]);
}
__global__ __launch_bounds__(128) void head2_kernel(
    const float* __restrict__ W, const float* __restrict__ bias,
    float* __restrict__ dout)
{
    int out = blockIdx.x*4 + (threadIdx.x >> 5);
    int lane = threadIdx.x & 31;
    int b = out / NCLS, c = out % NCLS;
    float s = 0.f;
    for (int d = lane; d < MLPD; d += 32) s += g_h1[b*MLPD + d]*W[(size_t)c*MLPD + d];
    #pragma unroll
    for (int off = 16; off; off >>= 1) s += __shfl_xor_sync(0xffffffffu, s, off);
    if (lane == 0) dout[out] = s + bias[c];
}

// ---------------- launch ---------------------------------------------------
extern "C" void kernel_launch(void* const* d_in, const int* in_sizes, int n_in,
                              void* d_out, int out_size) {
    const float* xyzs      = (const float*)d_in[0];
    const float* oldf      = (const float*)d_in[1];
    const float* conv_d_w  = (const float*)d_in[2];
    const float* conv_f_w  = (const float*)d_in[3];
    const float* pos_w     = (const float*)d_in[4];
    const float* pos_b     = (const float*)d_in[5];
    const float* contr_w   = (const float*)d_in[6];
    const float* contr_b   = (const float*)d_in[7];
    const float* ln1_s     = (const float*)d_in[8];
    const float* ln1_b     = (const float*)d_in[9];
    const float* qkv_w     = (const float*)d_in[10];
    const float* out_w     = (const float*)d_in[11];
    const float* out_b     = (const float*)d_in[12];
    const float* ln2_s     = (const float*)d_in[13];
    const float* ln2_b     = (const float*)d_in[14];
    const float* ff1_w     = (const float*)d_in[15];
    const float* ff1_b     = (const float*)d_in[16];
    const float* ff2_w     = (const float*)d_in[17];
    const float* ff2_b     = (const float*)d_in[18];
    const float* head_ln_s = (const float*)d_in[19];
    const float* head_ln_b = (const float*)d_in[20];
    const float* head1_w   = (const float*)d_in[21];
    const float* head1_b   = (const float*)d_in[22];
    const float* head2_w   = (const float*)d_in[23];
    const float* head2_b   = (const float*)d_in[24];
    float* out = (float*)d_out;

    float *px, *ppool, *phln;
    __nv_bfloat16 *pwh, *pwl, *phh, *phl, *pqh, *pql, *poh, *pol, *pf1h, *pf1l;
    cudaGetSymbolAddress((void**)&px,    g_x);
    cudaGetSymbolAddress((void**)&ppool, g_pool);
    cudaGetSymbolAddress((void**)&phln,  g_hln);
    cudaGetSymbolAddress((void**)&pwh,   g_wh);
    cudaGetSymbolAddress((void**)&pwl,   g_wl);
    cudaGetSymbolAddress((void**)&phh,   g_hh);
    cudaGetSymbolAddress((void**)&phl,   g_hl);
    cudaGetSymbolAddress((void**)&pqh,   g_qh);
    cudaGetSymbolAddress((void**)&pql,   g_ql);
    cudaGetSymbolAddress((void**)&poh,   g_oh);
    cudaGetSymbolAddress((void**)&pol,   g_ol);
    cudaGetSymbolAddress((void**)&pf1h,  g_f1h);
    cudaGetSymbolAddress((void**)&pf1l,  g_f1l);

    cudaFuncSetAttribute(flash_kernel, cudaFuncAttributeMaxDynamicSharedMemorySize, FA_SMEM);
    cudaFuncSetAttribute(tgemm_b, cudaFuncAttributeMaxDynamicSharedMemorySize, G_SMEM);
    cudaFuncSetAttribute(tgemm_b64, cudaFuncAttributeMaxDynamicSharedMemorySize, G64_SMEM);

    // ---- one-time weight split (single fused launch; graph-safe) ----
    wsplit_all_kernel<<<WTOT/1024, 256>>>(qkv_w, out_w, ff1_w, ff2_w, pwh, pwl);

    fps_kernel<<<48, 512>>>(xyzs);
    ball_kernel<<<(3*NTOK)/4, 128>>>(xyzs);
    conv_kernel<<<NTOK, 128>>>(xyzs, oldf, conv_d_w, conv_f_w, out);
    embed_kernel<<<NTOK, 512>>>(pos_w, pos_b, contr_w, contr_b, out);

    for (int l = 0; l < 4; l++) {
        ln_split_kernel<<<NTOK, 256>>>(px, ln1_s + l*EDIM, ln1_b + l*EDIM, phh, phl);
        // QKV: split output (Q pre-scaled by 1/8)
        tgemm_b<<<dim3(12,48,1), 256, G_SMEM>>>(
            phh, phl, pwh + WQKV_OFF + (size_t)l*1536*512, pwl + WQKV_OFF + (size_t)l*1536*512,
            nullptr, nullptr, pqh, pql,
            512, 512, 512, 1536, 0,0,0, 1,1);
        // fused attention -> o hi/lo (KV tile 64, 2 CTAs/SM)
        flash_kernel<<<dim3(LTOK/128, NB*NHEAD), 256, FA_SMEM>>>(pqh, pql, poh, pol);
        // out proj + residual (fp32 out) — BN=64
        tgemm_b64<<<dim3(8,48,1), 256, G64_SMEM>>>(
            poh, pol, pwh + WOUT_OFF + (size_t)l*512*512, pwl + WOUT_OFF + (size_t)l*512*512,
            out_b + l*EDIM, px, nullptr, nullptr,
            512, 512, 512, 512, 0,1,1, 0);
        ln_split_kernel<<<NTOK, 256>>>(px, ln2_s + l*EDIM, ln2_b + l*EDIM, phh, phl);
        // ff1 + gelu: split output — BN=64
        tgemm_b64<<<dim3(16,48,1), 256, G64_SMEM>>>(
            phh, phl, pwh + WFF1_OFF + (size_t)l*1024*512, pwl + WFF1_OFF + (size_t)l*1024*512,
            ff1_b + l*MLPD, nullptr, pf1h, pf1l,
            512, 512, 512, 1024, 1,0,1, 1);
        // ff2 + residual (fp32 out) — BN=64
        tgemm_b64<<<dim3(8,48,1), 256, G64_SMEM>>>(
            pf1h, pf1l, pwh + WFF2_OFF + (size_t)l*512*1024, pwl + WFF2_OFF + (size_t)l*512*1024,
            ff2_b + l*EDIM, px, nullptr, nullptr,
            1024, 1024, 1024, 512, 0,1,1, 0);
    }

    pool1_kernel<<<dim3(12, NB), 512>>>();
    pool2_kernel<<<NB, 512>>>();
    ln_kernel<<<NB, 256>>>(ppool, head_ln_s, head_ln_b, phln);
    head1_kernel<<<(NB*MLPD)/8, 256>>>(head1_w, head1_b);
    head2_kernel<<<NB*NCLS/4, 128>>>(head2_w, head2_b, out);
}